// round 1
// baseline (speedup 1.0000x reference)
#include <cuda_runtime.h>
#include <cuda_bf16.h>
#include <cstdint>

#define Bc 2
#define Lc 4096
#define Gc 256
#define HIDc 768
#define Hc 12
#define Dc 64
#define Wc 255
#define BLKc 128
#define Nc 32
#define Vc 32
#define SPLITc 17
#define KTOTG (Gc + Lc)   /* 4352 */
#define SCALEc 0.125f

// ---------------- device scratch (no allocations allowed) ----------------
__device__ float g_lq[Bc*Lc*HIDc];
__device__ float g_lk[Bc*Lc*HIDc];
__device__ float g_lv[Bc*Lc*HIDc];
__device__ float g_gq[Bc*Gc*HIDc];
__device__ float g_gk[Bc*Gc*HIDc];
__device__ float g_gv[Bc*Gc*HIDc];
__device__ float g_lctx[Bc*Lc*HIDc];
__device__ float g_gctx[Bc*Gc*HIDc];
__device__ unsigned char g_pl2l[Bc*Lc*Wc];
__device__ unsigned char g_pl2g[Bc*Lc*Gc];
__device__ unsigned char g_pg[Bc*Gc*KTOTG];
__device__ float g_part_acc[(size_t)Bc*Hc*SPLITc*Gc*Dc];
__device__ float g_part_m[Bc*Hc*SPLITc*Gc];
__device__ float g_part_l[Bc*Hc*SPLITc*Gc];

// ---------------- pack mask+id into one byte ----------------
__global__ void pack_l_kernel(const int* __restrict__ l2l_m, const int* __restrict__ l2l_i,
                              const int* __restrict__ l2g_m, const int* __restrict__ l2g_i) {
    int i = blockIdx.x * blockDim.x + threadIdx.x;
    const int nl = Bc*Lc*Wc;
    const int ng = Bc*Lc*Gc;
    if (i < nl) g_pl2l[i] = (unsigned char)((l2l_i[i] & 31) | (l2l_m[i] ? 0x80 : 0));
    if (i < ng) g_pl2g[i] = (unsigned char)((l2g_i[i] & 31) | (l2g_m[i] ? 0x80 : 0));
}

__global__ void pack_g_kernel(const int* __restrict__ gg_m, const int* __restrict__ gg_i,
                              const int* __restrict__ gl_m, const int* __restrict__ gl_i) {
    int i = blockIdx.x * blockDim.x + threadIdx.x;
    const int total = Bc*Gc*KTOTG;
    if (i >= total) return;
    int row = i / KTOTG, col = i % KTOTG;
    unsigned char v;
    if (col < Gc) { int idx = row*Gc + col;        v = (unsigned char)((gg_i[idx] & 31) | (gg_m[idx] ? 0x80 : 0)); }
    else          { int idx = row*Lc + (col - Gc); v = (unsigned char)((gl_i[idx] & 31) | (gl_m[idx] ? 0x80 : 0)); }
    g_pg[i] = v;
}

// ---------------- tiled SGEMM with bias:  C[M,768] = A[M,768] @ W[768,768] + b ----------------
template<int TM, int TN, int MM, int MN>
__global__ void gemm_bias(const float* __restrict__ A, const float* __restrict__ Wm,
                          const float* __restrict__ bias, float* __restrict__ C, int M) {
    constexpr int TK = 16;
    constexpr int TX = TN / MN;
    constexpr int TY = TM / MM;
    constexpr int NTHR = TX * TY;
    __shared__ float As[TK][TM + 4];
    __shared__ float Bs[TK][TN];
    const int tid = threadIdx.x;
    const int tx = tid % TX, ty = tid / TX;
    const int n0 = blockIdx.x * TN;
    const int m0 = blockIdx.y * TM;

    float acc[MM][MN];
    #pragma unroll
    for (int i = 0; i < MM; ++i)
        #pragma unroll
        for (int j = 0; j < MN; ++j) acc[i][j] = 0.f;

    for (int k0 = 0; k0 < HIDc; k0 += TK) {
        constexpr int AITER = TM*TK/NTHR;
        #pragma unroll
        for (int q2 = 0; q2 < AITER; ++q2) {
            int i = tid + q2*NTHR;
            int m = i / TK, kk = i % TK;
            As[kk][m] = A[(size_t)(m0 + m)*HIDc + k0 + kk];
        }
        constexpr int BITER = TK*TN/NTHR;
        #pragma unroll
        for (int q2 = 0; q2 < BITER; ++q2) {
            int i = tid + q2*NTHR;
            int kk = i / TN, n = i % TN;
            Bs[kk][n] = Wm[(size_t)(k0 + kk)*HIDc + n0 + n];
        }
        __syncthreads();
        #pragma unroll
        for (int kk = 0; kk < TK; ++kk) {
            float a[MM], bb[MN];
            #pragma unroll
            for (int i = 0; i < MM; ++i) a[i] = As[kk][ty*MM + i];
            #pragma unroll
            for (int j = 0; j < MN; ++j) bb[j] = Bs[kk][tx*MN + j];
            #pragma unroll
            for (int i = 0; i < MM; ++i)
                #pragma unroll
                for (int j = 0; j < MN; ++j) acc[i][j] += a[i]*bb[j];
        }
        __syncthreads();
    }
    #pragma unroll
    for (int i = 0; i < MM; ++i) {
        size_t crow = (size_t)(m0 + ty*MM + i)*HIDc + n0 + tx*MN;
        #pragma unroll
        for (int j = 0; j < MN; ++j)
            C[crow + j] = acc[i][j] + bias[n0 + tx*MN + j];
    }
}

// ---------------- long-token attention: one CTA per (b, block, head) ----------------
__global__ void __launch_bounds__(128) long_attn_kernel(
    const float* __restrict__ rel_emb, const float* __restrict__ rel_bias) {
    const int p = threadIdx.x;
    const int n = blockIdx.x;
    const int h = blockIdx.y;
    const int b = blockIdx.z;
    const int t = n*BLKc + p;

    __shared__ float sK[32][64];
    __shared__ float sV[32][64];
    __shared__ float sRE[32][64];
    __shared__ float sRel[128][33];

    float q[64];
    {
        const float4* qp = (const float4*)(g_lq + (((size_t)b*Lc + t)*Hc + h)*Dc);
        #pragma unroll
        for (int i = 0; i < 16; ++i) ((float4*)q)[i] = qp[i];
    }
    for (int i = p; i < Vc*Dc; i += 128)
        sRE[i >> 6][i & 63] = rel_emb[((i >> 6)*Hc + h)*Dc + (i & 63)];
    __syncthreads();

    #pragma unroll 1
    for (int r = 0; r < Vc; ++r) {
        float sum = 0.f;
        #pragma unroll
        for (int d = 0; d < 64; ++d) sum += q[d]*sRE[r][d];
        sRel[p][r] = sum + rel_bias[r*Hc + h];
    }

    float acc[64];
    #pragma unroll
    for (int d = 0; d < 64; ++d) acc[d] = 0.f;
    float mrun = -1e30f, lrun = 0.f;

    const unsigned char* prowL = g_pl2l + (size_t)(b*Lc + t)*Wc;
    const unsigned char* prowG = g_pl2g + (size_t)(b*Lc + t)*Gc;

    #pragma unroll 1
    for (int tile = 0; tile < 20; ++tile) {
        __syncthreads();
        if (tile < 12) {
            const int c0 = tile*32;
            #pragma unroll
            for (int it = 0; it < 4; ++it) {
                int idx = p + 128*it;
                int kk = idx >> 4, d4 = (idx & 15) << 2;
                int j = (n - 1)*BLKc + c0 + kk;
                float4 kv = make_float4(0.f,0.f,0.f,0.f), vv = make_float4(0.f,0.f,0.f,0.f);
                if (j >= 0 && j < Lc) {
                    size_t off = (((size_t)b*Lc + j)*Hc + h)*Dc + d4;
                    kv = *(const float4*)(g_lk + off);
                    vv = *(const float4*)(g_lv + off);
                }
                *(float4*)&sK[kk][d4] = kv;
                *(float4*)&sV[kk][d4] = vv;
            }
        } else {
            const int g0 = (tile - 12)*32;
            #pragma unroll
            for (int it = 0; it < 4; ++it) {
                int idx = p + 128*it;
                int kk = idx >> 4, d4 = (idx & 15) << 2;
                size_t off = (((size_t)b*Gc + g0 + kk)*Hc + h)*Dc + d4;
                *(float4*)&sK[kk][d4] = *(const float4*)(g_gk + off);
                *(float4*)&sV[kk][d4] = *(const float4*)(g_gv + off);
            }
        }
        __syncthreads();

        float s[32];
        float tmax = -1e30f;
        if (tile < 12) {
            const int c0 = tile*32;
            #pragma unroll
            for (int kk = 0; kk < 32; ++kk) {
                int c = c0 + kk;
                int r = c - p - 1;
                int j = (n - 1)*BLKc + c;
                bool valid = (r >= 0) && (r < Wc) && (j >= 0) && (j < Lc);
                unsigned char byt = prowL[valid ? r : 0];
                float dot = 0.f;
                #pragma unroll
                for (int d = 0; d < 64; ++d) dot += q[d]*sK[kk][d];
                float sc = (dot + sRel[p][byt & 31]) * SCALEc;
                if (!valid || !(byt & 0x80)) sc = -1e30f;
                s[kk] = sc;
                tmax = fmaxf(tmax, sc);
            }
        } else {
            const int g0 = (tile - 12)*32;
            #pragma unroll
            for (int kk = 0; kk < 32; ++kk) {
                unsigned char byt = prowG[g0 + kk];
                float dot = 0.f;
                #pragma unroll
                for (int d = 0; d < 64; ++d) dot += q[d]*sK[kk][d];
                float sc = (dot + sRel[p][byt & 31]) * SCALEc;
                if (!(byt & 0x80)) sc = -1e30f;
                s[kk] = sc;
                tmax = fmaxf(tmax, sc);
            }
        }

        float nm = fmaxf(mrun, tmax);
        float corr = __expf(mrun - nm);
        lrun *= corr;
        #pragma unroll
        for (int d = 0; d < 64; ++d) acc[d] *= corr;
        #pragma unroll
        for (int kk = 0; kk < 32; ++kk) {
            float pr = __expf(s[kk] - nm);
            lrun += pr;
            #pragma unroll
            for (int d = 0; d < 64; ++d) acc[d] += pr * sV[kk][d];
        }
        mrun = nm;
    }

    float inv = 1.f / lrun;
    #pragma unroll
    for (int d = 0; d < 64; ++d) q[d] = acc[d]*inv;
    float* op = g_lctx + (((size_t)b*Lc + t)*Hc + h)*Dc;
    #pragma unroll
    for (int i = 0; i < 16; ++i) ((float4*)op)[i] = ((float4*)q)[i];
}

// ---------------- global-token attention, split-K flash (partials) ----------------
__global__ void __launch_bounds__(128) glob_attn_kernel(
    const float* __restrict__ rel_emb, const float* __restrict__ rel_bias) {
    const int p = threadIdx.x;
    const int qb = blockIdx.x;       // 0..1
    const int split = blockIdx.y;    // 0..16
    const int bh = blockIdx.z;       // 0..23
    const int b = bh / Hc, h = bh % Hc;
    const int qi = qb*128 + p;

    __shared__ float sK[32][64];
    __shared__ float sV[32][64];
    __shared__ float sRE[32][64];
    __shared__ float sRel[128][33];

    float q[64];
    {
        const float4* qp = (const float4*)(g_gq + (((size_t)b*Gc + qi)*Hc + h)*Dc);
        #pragma unroll
        for (int i = 0; i < 16; ++i) ((float4*)q)[i] = qp[i];
    }
    for (int i = p; i < Vc*Dc; i += 128)
        sRE[i >> 6][i & 63] = rel_emb[((i >> 6)*Hc + h)*Dc + (i & 63)];
    __syncthreads();

    #pragma unroll 1
    for (int r = 0; r < Vc; ++r) {
        float sum = 0.f;
        #pragma unroll
        for (int d = 0; d < 64; ++d) sum += q[d]*sRE[r][d];
        sRel[p][r] = sum + rel_bias[r*Hc + h];
    }

    float acc[64];
    #pragma unroll
    for (int d = 0; d < 64; ++d) acc[d] = 0.f;
    float mrun = -1e30f, lrun = 0.f;

    const unsigned char* prow = g_pg + (size_t)(b*Gc + qi)*KTOTG;

    #pragma unroll 1
    for (int tt = 0; tt < 8; ++tt) {
        const int j0 = (split*8 + tt)*32;
        __syncthreads();
        #pragma unroll
        for (int it = 0; it < 4; ++it) {
            int idx = p + 128*it;
            int kk = idx >> 4, d4 = (idx & 15) << 2;
            int j = j0 + kk;
            const float *kp, *vp;
            size_t off;
            if (j < Gc) { off = (((size_t)b*Gc + j)*Hc + h)*Dc + d4;        kp = g_gk; vp = g_gv; }
            else        { off = (((size_t)b*Lc + (j - Gc))*Hc + h)*Dc + d4; kp = g_lk; vp = g_lv; }
            *(float4*)&sK[kk][d4] = *(const float4*)(kp + off);
            *(float4*)&sV[kk][d4] = *(const float4*)(vp + off);
        }
        __syncthreads();

        float s[32];
        float tmax = -1e30f;
        #pragma unroll
        for (int kk = 0; kk < 32; ++kk) {
            unsigned char byt = prow[j0 + kk];
            float dot = 0.f;
            #pragma unroll
            for (int d = 0; d < 64; ++d) dot += q[d]*sK[kk][d];
            float sc = (dot + sRel[p][byt & 31]) * SCALEc;
            if (!(byt & 0x80)) sc = -1e30f;
            s[kk] = sc;
            tmax = fmaxf(tmax, sc);
        }

        float nm = fmaxf(mrun, tmax);
        float corr = __expf(mrun - nm);
        lrun *= corr;
        #pragma unroll
        for (int d = 0; d < 64; ++d) acc[d] *= corr;
        #pragma unroll
        for (int kk = 0; kk < 32; ++kk) {
            float pr = __expf(s[kk] - nm);
            lrun += pr;
            #pragma unroll
            for (int d = 0; d < 64; ++d) acc[d] += pr * sV[kk][d];
        }
        mrun = nm;
    }

    const int pi = bh*SPLITc + split;
    const size_t base = (size_t)pi*Gc + qi;
    g_part_m[base] = mrun;
    g_part_l[base] = lrun;
    float* pa = g_part_acc + base*Dc;
    #pragma unroll
    for (int i = 0; i < 16; ++i) ((float4*)pa)[i] = ((float4*)acc)[i];
}

__global__ void glob_combine_kernel() {
    const int row = blockIdx.x;       // bh*Gc + qi
    const int d = threadIdx.x;        // 0..63
    const int bh = row >> 8;
    const int qi = row & 255;
    const int b = bh / Hc, h = bh % Hc;
    float M = -1e30f;
    #pragma unroll 1
    for (int s = 0; s < SPLITc; ++s)
        M = fmaxf(M, g_part_m[(size_t)(bh*SPLITc + s)*Gc + qi]);
    float L = 0.f, a = 0.f;
    #pragma unroll 1
    for (int s = 0; s < SPLITc; ++s) {
        size_t base = (size_t)(bh*SPLITc + s)*Gc + qi;
        float w = __expf(g_part_m[base] - M);
        L += w * g_part_l[base];
        a += w * g_part_acc[base*Dc + d];
    }
    g_gctx[(((size_t)b*Gc + qi)*Hc + h)*Dc + d] = a / L;
}

// ---------------- host launcher ----------------
extern "C" void kernel_launch(void* const* d_in, const int* in_sizes, int n_in,
                              void* d_out, int out_size) {
    (void)in_sizes; (void)n_in; (void)out_size;

    const float* long_input   = (const float*)d_in[0];
    const float* global_input = (const float*)d_in[1];
    const int* l2l_m = (const int*)d_in[2];
    const int* g2g_m = (const int*)d_in[3];
    const int* l2g_m = (const int*)d_in[4];
    const int* g2l_m = (const int*)d_in[5];
    const int* l2l_i = (const int*)d_in[6];
    const int* g2g_i = (const int*)d_in[7];
    const int* l2g_i = (const int*)d_in[8];
    const int* g2l_i = (const int*)d_in[9];
    const float* wq_long = (const float*)d_in[10];
    const float* bq_long = (const float*)d_in[11];
    const float* wk_long = (const float*)d_in[12];
    const float* bk_long = (const float*)d_in[13];
    const float* wv_long = (const float*)d_in[14];
    const float* bv_long = (const float*)d_in[15];
    const float* wq_glob = (const float*)d_in[16];
    const float* bq_glob = (const float*)d_in[17];
    const float* wk_glob = (const float*)d_in[18];
    const float* bk_glob = (const float*)d_in[19];
    const float* wv_glob = (const float*)d_in[20];
    const float* bv_glob = (const float*)d_in[21];
    const float* rel_emb_long  = (const float*)d_in[22];
    const float* rel_bias_long = (const float*)d_in[23];
    const float* rel_emb_glob  = (const float*)d_in[24];
    const float* rel_bias_glob = (const float*)d_in[25];
    const float* wo_long = (const float*)d_in[26];
    const float* bo_long = (const float*)d_in[27];
    const float* wo_glob = (const float*)d_in[28];
    const float* bo_glob = (const float*)d_in[29];

    float *lq, *lk, *lv, *gq, *gk, *gv, *lctx, *gctx;
    cudaGetSymbolAddress((void**)&lq,   g_lq);
    cudaGetSymbolAddress((void**)&lk,   g_lk);
    cudaGetSymbolAddress((void**)&lv,   g_lv);
    cudaGetSymbolAddress((void**)&gq,   g_gq);
    cudaGetSymbolAddress((void**)&gk,   g_gk);
    cudaGetSymbolAddress((void**)&gv,   g_gv);
    cudaGetSymbolAddress((void**)&lctx, g_lctx);
    cudaGetSymbolAddress((void**)&gctx, g_gctx);

    // 1) pack mask+id bytes
    {
        int nmax = Bc*Lc*Gc;  // >= Bc*Lc*Wc
        pack_l_kernel<<<(nmax + 255)/256, 256>>>(l2l_m, l2l_i, l2g_m, l2g_i);
        int ntot = Bc*Gc*KTOTG;
        pack_g_kernel<<<(ntot + 255)/256, 256>>>(g2g_m, g2g_i, g2l_m, g2l_i);
    }

    // 2) projections
    dim3 gbig(HIDc/128, (Bc*Lc)/128);   // (6, 64)
    dim3 gsm (HIDc/64,  (Bc*Gc)/64);    // (12, 8)
    gemm_bias<128,128,8,8><<<gbig, 256>>>(long_input, wq_long, bq_long, lq, Bc*Lc);
    gemm_bias<128,128,8,8><<<gbig, 256>>>(long_input, wk_long, bk_long, lk, Bc*Lc);
    gemm_bias<128,128,8,8><<<gbig, 256>>>(long_input, wv_long, bv_long, lv, Bc*Lc);
    gemm_bias<64,64,8,4><<<gsm, 128>>>(global_input, wq_glob, bq_glob, gq, Bc*Gc);
    gemm_bias<64,64,8,4><<<gsm, 128>>>(global_input, wk_glob, bk_glob, gk, Bc*Gc);
    gemm_bias<64,64,8,4><<<gsm, 128>>>(global_input, wv_glob, bv_glob, gv, Bc*Gc);

    // 3) long attention
    dim3 gla(Nc, Hc, Bc);
    long_attn_kernel<<<gla, 128>>>(rel_emb_long, rel_bias_long);

    // 4) global attention (split-K + combine)
    dim3 gga(2, SPLITc, Bc*Hc);
    glob_attn_kernel<<<gga, 128>>>(rel_emb_glob, rel_bias_glob);
    glob_combine_kernel<<<Bc*Hc*Gc, 64>>>();

    // 5) output projections directly into d_out  (long_out then glob_out)
    float* out_long = (float*)d_out;
    float* out_glob = out_long + (size_t)Bc*Lc*HIDc;
    gemm_bias<128,128,8,8><<<gbig, 256>>>(lctx, wo_long, bo_long, out_long, Bc*Lc);
    gemm_bias<64,64,8,4><<<gsm, 128>>>(gctx, wo_glob, bo_glob, out_glob, Bc*Gc);
}

// round 4
// speedup vs baseline: 1.3866x; 1.3866x over previous
#include <cuda_runtime.h>
#include <cuda_bf16.h>
#include <cstdint>

#define Bc 2
#define Lc 4096
#define Gc 256
#define HIDc 768
#define Hc 12
#define Dc 64
#define Wc 255
#define BLKc 128
#define Nc 32
#define Vc 32
#define SPLITc 17
#define KTOTG (Gc + Lc)   /* 4352 */
#define SCALEc 0.125f

// ---------------- device scratch (no allocations allowed) ----------------
__device__ float g_lq[Bc*Lc*HIDc];
__device__ float g_lk[Bc*Lc*HIDc];
__device__ float g_lv[Bc*Lc*HIDc];
__device__ float g_gq[Bc*Gc*HIDc];
__device__ float g_gk[Bc*Gc*HIDc];
__device__ float g_gv[Bc*Gc*HIDc];
__device__ float g_lctx[Bc*Lc*HIDc];
__device__ float g_gctx[Bc*Gc*HIDc];
__device__ unsigned char g_pl2l[Bc*Lc*Wc];
__device__ unsigned char g_pl2g[Bc*Lc*Gc];
__device__ unsigned char g_pg[Bc*Gc*KTOTG];
__device__ float g_part_acc[(size_t)Bc*Hc*SPLITc*Gc*Dc];
__device__ float g_part_m[Bc*Hc*SPLITc*Gc];
__device__ float g_part_l[Bc*Hc*SPLITc*Gc];

// =============== TF32 mma.sync GEMM: C[M,768] = A[M,768] @ W[768,768] + b ===============
// CTA tile 128x128, 8 warps (2 M x 4 N), warp tile 64x32 = 4x4 m16n8k8 frags, K-chunk 32.
__device__ __forceinline__ uint32_t to_tf32(float f) {
    uint32_t r;
    asm("cvt.rna.tf32.f32 %0, %1;" : "=r"(r) : "f"(f));
    return r;
}

#define APAD 36
#define BPAD 136

__global__ void __launch_bounds__(256) gemm_mma(
    const float* __restrict__ A, const float* __restrict__ Wm,
    const float* __restrict__ bias, float* __restrict__ C) {
    __shared__ uint32_t As[128 * APAD];
    __shared__ uint32_t Bs[32 * BPAD];
    const int tid = threadIdx.x;
    const int warp = tid >> 5, lane = tid & 31;
    const int g = lane >> 2, tg = lane & 3;
    const int wm = (warp >> 2) * 64;      // 0 or 64
    const int wn = (warp & 3) * 32;       // 0,32,64,96
    const int m0 = blockIdx.y * 128;
    const int n0 = blockIdx.x * 128;

    float acc[4][4][4];
    #pragma unroll
    for (int mi = 0; mi < 4; ++mi)
        #pragma unroll
        for (int ni = 0; ni < 4; ++ni)
            #pragma unroll
            for (int c = 0; c < 4; ++c) acc[mi][ni][c] = 0.f;

    #pragma unroll 1
    for (int ch = 0; ch < 24; ++ch) {
        const int k0 = ch * 32;
        // A tile: 128 rows x 32 k (float4 loads, cvt to tf32 at store)
        #pragma unroll
        for (int it = 0; it < 4; ++it) {
            int lin = tid + it * 256;           // 0..1023
            int row = lin >> 3, f4 = lin & 7;
            float4 v = *(const float4*)(A + (size_t)(m0 + row) * HIDc + k0 + f4 * 4);
            uint32_t* dst = &As[row * APAD + f4 * 4];
            dst[0] = to_tf32(v.x); dst[1] = to_tf32(v.y);
            dst[2] = to_tf32(v.z); dst[3] = to_tf32(v.w);
        }
        // B tile: 32 k-rows x 128 n (coalesced along n)
        #pragma unroll
        for (int it = 0; it < 16; ++it) {
            int lin = tid + it * 256;           // 0..4095
            int kk = lin >> 7, nn = lin & 127;
            Bs[kk * BPAD + nn] = to_tf32(Wm[(size_t)(k0 + kk) * HIDc + n0 + nn]);
        }
        __syncthreads();

        #pragma unroll
        for (int ks = 0; ks < 32; ks += 8) {
            uint32_t af[4][4], bf[4][2];
            #pragma unroll
            for (int mi = 0; mi < 4; ++mi) {
                int mb = wm + mi * 16;
                af[mi][0] = As[(mb + g) * APAD + ks + tg];
                af[mi][1] = As[(mb + g + 8) * APAD + ks + tg];
                af[mi][2] = As[(mb + g) * APAD + ks + tg + 4];
                af[mi][3] = As[(mb + g + 8) * APAD + ks + tg + 4];
            }
            #pragma unroll
            for (int ni = 0; ni < 4; ++ni) {
                int nb = wn + ni * 8 + g;
                bf[ni][0] = Bs[(ks + tg) * BPAD + nb];
                bf[ni][1] = Bs[(ks + tg + 4) * BPAD + nb];
            }
            #pragma unroll
            for (int mi = 0; mi < 4; ++mi)
                #pragma unroll
                for (int ni = 0; ni < 4; ++ni)
                    asm volatile(
                        "mma.sync.aligned.m16n8k8.row.col.f32.tf32.tf32.f32 "
                        "{%0,%1,%2,%3}, {%4,%5,%6,%7}, {%8,%9}, {%0,%1,%2,%3};"
                        : "+f"(acc[mi][ni][0]), "+f"(acc[mi][ni][1]),
                          "+f"(acc[mi][ni][2]), "+f"(acc[mi][ni][3])
                        : "r"(af[mi][0]), "r"(af[mi][1]), "r"(af[mi][2]), "r"(af[mi][3]),
                          "r"(bf[ni][0]), "r"(bf[ni][1]));
        }
        __syncthreads();
    }

    // Epilogue: c0,c1 -> (row g, cols 2*tg, 2*tg+1); c2,c3 -> row g+8
    #pragma unroll
    for (int mi = 0; mi < 4; ++mi) {
        #pragma unroll
        for (int ni = 0; ni < 4; ++ni) {
            int r0 = m0 + wm + mi * 16 + g;
            int cc = n0 + wn + ni * 8 + 2 * tg;
            float2 b2 = *(const float2*)(bias + cc);
            float2 v0 = make_float2(acc[mi][ni][0] + b2.x, acc[mi][ni][1] + b2.y);
            float2 v1 = make_float2(acc[mi][ni][2] + b2.x, acc[mi][ni][3] + b2.y);
            *(float2*)(C + (size_t)r0 * HIDc + cc) = v0;
            *(float2*)(C + (size_t)(r0 + 8) * HIDc + cc) = v1;
        }
    }
}

// ---------------- pack mask+id into one byte ----------------
__global__ void pack_l_kernel(const int* __restrict__ l2l_m, const int* __restrict__ l2l_i,
                              const int* __restrict__ l2g_m, const int* __restrict__ l2g_i) {
    int i = blockIdx.x * blockDim.x + threadIdx.x;
    const int nl = Bc*Lc*Wc;
    const int ng = Bc*Lc*Gc;
    if (i < nl) g_pl2l[i] = (unsigned char)((l2l_i[i] & 31) | (l2l_m[i] ? 0x80 : 0));
    if (i < ng) g_pl2g[i] = (unsigned char)((l2g_i[i] & 31) | (l2g_m[i] ? 0x80 : 0));
}

__global__ void pack_g_kernel(const int* __restrict__ gg_m, const int* __restrict__ gg_i,
                              const int* __restrict__ gl_m, const int* __restrict__ gl_i) {
    int i = blockIdx.x * blockDim.x + threadIdx.x;
    const int total = Bc*Gc*KTOTG;
    if (i >= total) return;
    int row = i / KTOTG, col = i % KTOTG;
    unsigned char v;
    if (col < Gc) { int idx = row*Gc + col;        v = (unsigned char)((gg_i[idx] & 31) | (gg_m[idx] ? 0x80 : 0)); }
    else          { int idx = row*Lc + (col - Gc); v = (unsigned char)((gl_i[idx] & 31) | (gl_m[idx] ? 0x80 : 0)); }
    g_pg[i] = v;
}

// ---------------- fp32 tiled SGEMM (small M only) ----------------
template<int TM, int TN, int MM, int MN>
__global__ void gemm_bias(const float* __restrict__ A, const float* __restrict__ Wm,
                          const float* __restrict__ bias, float* __restrict__ C, int M) {
    constexpr int TK = 16;
    constexpr int TX = TN / MN;
    constexpr int TY = TM / MM;
    constexpr int NTHR = TX * TY;
    __shared__ float As[TK][TM + 4];
    __shared__ float Bs[TK][TN];
    const int tid = threadIdx.x;
    const int tx = tid % TX, ty = tid / TX;
    const int n0 = blockIdx.x * TN;
    const int m0 = blockIdx.y * TM;

    float acc[MM][MN];
    #pragma unroll
    for (int i = 0; i < MM; ++i)
        #pragma unroll
        for (int j = 0; j < MN; ++j) acc[i][j] = 0.f;

    for (int k0 = 0; k0 < HIDc; k0 += TK) {
        constexpr int AITER = TM*TK/NTHR;
        #pragma unroll
        for (int q2 = 0; q2 < AITER; ++q2) {
            int i = tid + q2*NTHR;
            int m = i / TK, kk = i % TK;
            As[kk][m] = A[(size_t)(m0 + m)*HIDc + k0 + kk];
        }
        constexpr int BITER = TK*TN/NTHR;
        #pragma unroll
        for (int q2 = 0; q2 < BITER; ++q2) {
            int i = tid + q2*NTHR;
            int kk = i / TN, n = i % TN;
            Bs[kk][n] = Wm[(size_t)(k0 + kk)*HIDc + n0 + n];
        }
        __syncthreads();
        #pragma unroll
        for (int kk = 0; kk < TK; ++kk) {
            float a[MM], bb[MN];
            #pragma unroll
            for (int i = 0; i < MM; ++i) a[i] = As[kk][ty*MM + i];
            #pragma unroll
            for (int j = 0; j < MN; ++j) bb[j] = Bs[kk][tx*MN + j];
            #pragma unroll
            for (int i = 0; i < MM; ++i)
                #pragma unroll
                for (int j = 0; j < MN; ++j) acc[i][j] += a[i]*bb[j];
        }
        __syncthreads();
    }
    #pragma unroll
    for (int i = 0; i < MM; ++i) {
        size_t crow = (size_t)(m0 + ty*MM + i)*HIDc + n0 + tx*MN;
        #pragma unroll
        for (int j = 0; j < MN; ++j)
            C[crow + j] = acc[i][j] + bias[n0 + tx*MN + j];
    }
}

// ---------------- long-token attention: one CTA per (b, block, head) ----------------
__global__ void __launch_bounds__(128) long_attn_kernel(
    const float* __restrict__ rel_emb, const float* __restrict__ rel_bias) {
    const int p = threadIdx.x;
    const int n = blockIdx.x;
    const int h = blockIdx.y;
    const int b = blockIdx.z;
    const int t = n*BLKc + p;

    __shared__ float sK[32][64];
    __shared__ float sV[32][64];
    __shared__ float sRE[32][64];
    __shared__ float sRel[128][33];

    float q[64];
    {
        const float4* qp = (const float4*)(g_lq + (((size_t)b*Lc + t)*Hc + h)*Dc);
        #pragma unroll
        for (int i = 0; i < 16; ++i) ((float4*)q)[i] = qp[i];
    }
    for (int i = p; i < Vc*Dc; i += 128)
        sRE[i >> 6][i & 63] = rel_emb[((i >> 6)*Hc + h)*Dc + (i & 63)];
    __syncthreads();

    #pragma unroll 1
    for (int r = 0; r < Vc; ++r) {
        float sum = 0.f;
        #pragma unroll
        for (int d = 0; d < 64; ++d) sum += q[d]*sRE[r][d];
        sRel[p][r] = sum + rel_bias[r*Hc + h];
    }

    float acc[64];
    #pragma unroll
    for (int d = 0; d < 64; ++d) acc[d] = 0.f;
    float mrun = -1e30f, lrun = 0.f;

    const unsigned char* prowL = g_pl2l + (size_t)(b*Lc + t)*Wc;
    const unsigned char* prowG = g_pl2g + (size_t)(b*Lc + t)*Gc;

    #pragma unroll 1
    for (int tile = 0; tile < 20; ++tile) {
        __syncthreads();
        if (tile < 12) {
            const int c0 = tile*32;
            #pragma unroll
            for (int it = 0; it < 4; ++it) {
                int idx = p + 128*it;
                int kk = idx >> 4, d4 = (idx & 15) << 2;
                int j = (n - 1)*BLKc + c0 + kk;
                float4 kv = make_float4(0.f,0.f,0.f,0.f), vv = make_float4(0.f,0.f,0.f,0.f);
                if (j >= 0 && j < Lc) {
                    size_t off = (((size_t)b*Lc + j)*Hc + h)*Dc + d4;
                    kv = *(const float4*)(g_lk + off);
                    vv = *(const float4*)(g_lv + off);
                }
                *(float4*)&sK[kk][d4] = kv;
                *(float4*)&sV[kk][d4] = vv;
            }
        } else {
            const int g0 = (tile - 12)*32;
            #pragma unroll
            for (int it = 0; it < 4; ++it) {
                int idx = p + 128*it;
                int kk = idx >> 4, d4 = (idx & 15) << 2;
                size_t off = (((size_t)b*Gc + g0 + kk)*Hc + h)*Dc + d4;
                *(float4*)&sK[kk][d4] = *(const float4*)(g_gk + off);
                *(float4*)&sV[kk][d4] = *(const float4*)(g_gv + off);
            }
        }
        __syncthreads();

        float s[32];
        float tmax = -1e30f;
        if (tile < 12) {
            const int c0 = tile*32;
            #pragma unroll
            for (int kk = 0; kk < 32; ++kk) {
                int c = c0 + kk;
                int r = c - p - 1;
                int j = (n - 1)*BLKc + c;
                bool valid = (r >= 0) && (r < Wc) && (j >= 0) && (j < Lc);
                unsigned char byt = prowL[valid ? r : 0];
                float dot = 0.f;
                #pragma unroll
                for (int d = 0; d < 64; ++d) dot += q[d]*sK[kk][d];
                float sc = (dot + sRel[p][byt & 31]) * SCALEc;
                if (!valid || !(byt & 0x80)) sc = -1e30f;
                s[kk] = sc;
                tmax = fmaxf(tmax, sc);
            }
        } else {
            const int g0 = (tile - 12)*32;
            #pragma unroll
            for (int kk = 0; kk < 32; ++kk) {
                unsigned char byt = prowG[g0 + kk];
                float dot = 0.f;
                #pragma unroll
                for (int d = 0; d < 64; ++d) dot += q[d]*sK[kk][d];
                float sc = (dot + sRel[p][byt & 31]) * SCALEc;
                if (!(byt & 0x80)) sc = -1e30f;
                s[kk] = sc;
                tmax = fmaxf(tmax, sc);
            }
        }

        float nm = fmaxf(mrun, tmax);
        float corr = __expf(mrun - nm);
        lrun *= corr;
        #pragma unroll
        for (int d = 0; d < 64; ++d) acc[d] *= corr;
        #pragma unroll
        for (int kk = 0; kk < 32; ++kk) {
            float pr = __expf(s[kk] - nm);
            lrun += pr;
            #pragma unroll
            for (int d = 0; d < 64; ++d) acc[d] += pr * sV[kk][d];
        }
        mrun = nm;
    }

    float inv = 1.f / lrun;
    #pragma unroll
    for (int d = 0; d < 64; ++d) q[d] = acc[d]*inv;
    float* op = g_lctx + (((size_t)b*Lc + t)*Hc + h)*Dc;
    #pragma unroll
    for (int i = 0; i < 16; ++i) ((float4*)op)[i] = ((float4*)q)[i];
}

// ---------------- global-token attention, split-K flash (partials) ----------------
__global__ void __launch_bounds__(128) glob_attn_kernel(
    const float* __restrict__ rel_emb, const float* __restrict__ rel_bias) {
    const int p = threadIdx.x;
    const int qb = blockIdx.x;       // 0..1
    const int split = blockIdx.y;    // 0..16
    const int bh = blockIdx.z;       // 0..23
    const int b = bh / Hc, h = bh % Hc;
    const int qi = qb*128 + p;

    __shared__ float sK[32][64];
    __shared__ float sV[32][64];
    __shared__ float sRE[32][64];
    __shared__ float sRel[128][33];

    float q[64];
    {
        const float4* qp = (const float4*)(g_gq + (((size_t)b*Gc + qi)*Hc + h)*Dc);
        #pragma unroll
        for (int i = 0; i < 16; ++i) ((float4*)q)[i] = qp[i];
    }
    for (int i = p; i < Vc*Dc; i += 128)
        sRE[i >> 6][i & 63] = rel_emb[((i >> 6)*Hc + h)*Dc + (i & 63)];
    __syncthreads();

    #pragma unroll 1
    for (int r = 0; r < Vc; ++r) {
        float sum = 0.f;
        #pragma unroll
        for (int d = 0; d < 64; ++d) sum += q[d]*sRE[r][d];
        sRel[p][r] = sum + rel_bias[r*Hc + h];
    }

    float acc[64];
    #pragma unroll
    for (int d = 0; d < 64; ++d) acc[d] = 0.f;
    float mrun = -1e30f, lrun = 0.f;

    const unsigned char* prow = g_pg + (size_t)(b*Gc + qi)*KTOTG;

    #pragma unroll 1
    for (int tt = 0; tt < 8; ++tt) {
        const int j0 = (split*8 + tt)*32;
        __syncthreads();
        #pragma unroll
        for (int it = 0; it < 4; ++it) {
            int idx = p + 128*it;
            int kk = idx >> 4, d4 = (idx & 15) << 2;
            int j = j0 + kk;
            const float *kp, *vp;
            size_t off;
            if (j < Gc) { off = (((size_t)b*Gc + j)*Hc + h)*Dc + d4;        kp = g_gk; vp = g_gv; }
            else        { off = (((size_t)b*Lc + (j - Gc))*Hc + h)*Dc + d4; kp = g_lk; vp = g_lv; }
            *(float4*)&sK[kk][d4] = *(const float4*)(kp + off);
            *(float4*)&sV[kk][d4] = *(const float4*)(vp + off);
        }
        __syncthreads();

        float s[32];
        float tmax = -1e30f;
        #pragma unroll
        for (int kk = 0; kk < 32; ++kk) {
            unsigned char byt = prow[j0 + kk];
            float dot = 0.f;
            #pragma unroll
            for (int d = 0; d < 64; ++d) dot += q[d]*sK[kk][d];
            float sc = (dot + sRel[p][byt & 31]) * SCALEc;
            if (!(byt & 0x80)) sc = -1e30f;
            s[kk] = sc;
            tmax = fmaxf(tmax, sc);
        }

        float nm = fmaxf(mrun, tmax);
        float corr = __expf(mrun - nm);
        lrun *= corr;
        #pragma unroll
        for (int d = 0; d < 64; ++d) acc[d] *= corr;
        #pragma unroll
        for (int kk = 0; kk < 32; ++kk) {
            float pr = __expf(s[kk] - nm);
            lrun += pr;
            #pragma unroll
            for (int d = 0; d < 64; ++d) acc[d] += pr * sV[kk][d];
        }
        mrun = nm;
    }

    const int pi = bh*SPLITc + split;
    const size_t base = (size_t)pi*Gc + qi;
    g_part_m[base] = mrun;
    g_part_l[base] = lrun;
    float* pa = g_part_acc + base*Dc;
    #pragma unroll
    for (int i = 0; i < 16; ++i) ((float4*)pa)[i] = ((float4*)acc)[i];
}

__global__ void glob_combine_kernel() {
    const int row = blockIdx.x;       // bh*Gc + qi
    const int d = threadIdx.x;        // 0..63
    const int bh = row >> 8;
    const int qi = row & 255;
    const int b = bh / Hc, h = bh % Hc;
    float M = -1e30f;
    #pragma unroll 1
    for (int s = 0; s < SPLITc; ++s)
        M = fmaxf(M, g_part_m[(size_t)(bh*SPLITc + s)*Gc + qi]);
    float L = 0.f, a = 0.f;
    #pragma unroll 1
    for (int s = 0; s < SPLITc; ++s) {
        size_t base = (size_t)(bh*SPLITc + s)*Gc + qi;
        float w = __expf(g_part_m[base] - M);
        L += w * g_part_l[base];
        a += w * g_part_acc[base*Dc + d];
    }
    g_gctx[(((size_t)b*Gc + qi)*Hc + h)*Dc + d] = a / L;
}

// ---------------- host launcher ----------------
extern "C" void kernel_launch(void* const* d_in, const int* in_sizes, int n_in,
                              void* d_out, int out_size) {
    (void)in_sizes; (void)n_in; (void)out_size;

    const float* long_input   = (const float*)d_in[0];
    const float* global_input = (const float*)d_in[1];
    const int* l2l_m = (const int*)d_in[2];
    const int* g2g_m = (const int*)d_in[3];
    const int* l2g_m = (const int*)d_in[4];
    const int* g2l_m = (const int*)d_in[5];
    const int* l2l_i = (const int*)d_in[6];
    const int* g2g_i = (const int*)d_in[7];
    const int* l2g_i = (const int*)d_in[8];
    const int* g2l_i = (const int*)d_in[9];
    const float* wq_long = (const float*)d_in[10];
    const float* bq_long = (const float*)d_in[11];
    const float* wk_long = (const float*)d_in[12];
    const float* bk_long = (const float*)d_in[13];
    const float* wv_long = (const float*)d_in[14];
    const float* bv_long = (const float*)d_in[15];
    const float* wq_glob = (const float*)d_in[16];
    const float* bq_glob = (const float*)d_in[17];
    const float* wk_glob = (const float*)d_in[18];
    const float* bk_glob = (const float*)d_in[19];
    const float* wv_glob = (const float*)d_in[20];
    const float* bv_glob = (const float*)d_in[21];
    const float* rel_emb_long  = (const float*)d_in[22];
    const float* rel_bias_long = (const float*)d_in[23];
    const float* rel_emb_glob  = (const float*)d_in[24];
    const float* rel_bias_glob = (const float*)d_in[25];
    const float* wo_long = (const float*)d_in[26];
    const float* bo_long = (const float*)d_in[27];
    const float* wo_glob = (const float*)d_in[28];
    const float* bo_glob = (const float*)d_in[29];

    float *lq, *lk, *lv, *gq, *gk, *gv, *lctx, *gctx;
    cudaGetSymbolAddress((void**)&lq,   g_lq);
    cudaGetSymbolAddress((void**)&lk,   g_lk);
    cudaGetSymbolAddress((void**)&lv,   g_lv);
    cudaGetSymbolAddress((void**)&gq,   g_gq);
    cudaGetSymbolAddress((void**)&gk,   g_gk);
    cudaGetSymbolAddress((void**)&gv,   g_gv);
    cudaGetSymbolAddress((void**)&lctx, g_lctx);
    cudaGetSymbolAddress((void**)&gctx, g_gctx);

    // 1) pack mask+id bytes
    {
        int nmax = Bc*Lc*Gc;  // >= Bc*Lc*Wc
        pack_l_kernel<<<(nmax + 255)/256, 256>>>(l2l_m, l2l_i, l2g_m, l2g_i);
        int ntot = Bc*Gc*KTOTG;
        pack_g_kernel<<<(ntot + 255)/256, 256>>>(g2g_m, g2g_i, g2l_m, g2l_i);
    }

    // 2) projections (big ones via mma.sync TF32)
    dim3 gbig(HIDc/128, (Bc*Lc)/128);   // (6, 64)
    dim3 gsm (HIDc/64,  (Bc*Gc)/64);    // (12, 8)
    gemm_mma<<<gbig, 256>>>(long_input, wq_long, bq_long, lq);
    gemm_mma<<<gbig, 256>>>(long_input, wk_long, bk_long, lk);
    gemm_mma<<<gbig, 256>>>(long_input, wv_long, bv_long, lv);
    gemm_bias<64,64,8,4><<<gsm, 128>>>(global_input, wq_glob, bq_glob, gq, Bc*Gc);
    gemm_bias<64,64,8,4><<<gsm, 128>>>(global_input, wk_glob, bk_glob, gk, Bc*Gc);
    gemm_bias<64,64,8,4><<<gsm, 128>>>(global_input, wv_glob, bv_glob, gv, Bc*Gc);

    // 3) long attention
    dim3 gla(Nc, Hc, Bc);
    long_attn_kernel<<<gla, 128>>>(rel_emb_long, rel_bias_long);

    // 4) global attention (split-K + combine)
    dim3 gga(2, SPLITc, Bc*Hc);
    glob_attn_kernel<<<gga, 128>>>(rel_emb_glob, rel_bias_glob);
    glob_combine_kernel<<<Bc*Hc*Gc, 64>>>();

    // 5) output projections directly into d_out  (long_out then glob_out)
    float* out_long = (float*)d_out;
    float* out_glob = out_long + (size_t)Bc*Lc*HIDc;
    gemm_mma<<<gbig, 256>>>(lctx, wo_long, bo_long, out_long);
    gemm_bias<64,64,8,4><<<gsm, 128>>>(gctx, wo_glob, bo_glob, out_glob, Bc*Gc);
}

// round 5
// speedup vs baseline: 2.2190x; 1.6002x over previous
#include <cuda_runtime.h>
#include <cuda_bf16.h>
#include <cstdint>

#define Bc 2
#define Lc 4096
#define Gc 256
#define HIDc 768
#define Hc 12
#define Dc 64
#define Wc 255
#define BLKc 128
#define Nc 32
#define Vc 32
#define KTOTG (Gc + Lc)   /* 4352 */
#define SCALEc 0.125f
#define GSPLIT 4          /* key splits for global attention (68 tiles = 4*17) */

// ---------------- device scratch (no allocations allowed) ----------------
__device__ float g_lq[Bc*Lc*HIDc];
__device__ float g_lk[Bc*Lc*HIDc];
__device__ float g_lv[Bc*Lc*HIDc];
__device__ float g_gq[Bc*Gc*HIDc];
__device__ float g_gk[Bc*Gc*HIDc];
__device__ float g_gv[Bc*Gc*HIDc];
__device__ float g_lctx[Bc*Lc*HIDc];
__device__ float g_gctx[Bc*Gc*HIDc];
__device__ unsigned char g_pl2l[Bc*Lc*Wc];
__device__ unsigned char g_pl2g[Bc*Lc*Gc];
__device__ unsigned char g_pg[Bc*Gc*KTOTG];
__device__ float g_part_acc[(size_t)Bc*Hc*2*GSPLIT*128*64];
__device__ float g_part_l[Bc*Hc*2*GSPLIT*128];

// ---------------- helpers ----------------
__device__ __forceinline__ uint32_t to_tf32(float f) {
    uint32_t r;
    asm("cvt.rna.tf32.f32 %0, %1;" : "=r"(r) : "f"(f));
    return r;
}
__device__ __forceinline__ void mma8(float* c, const uint32_t* a, uint32_t b0, uint32_t b1) {
    asm volatile("mma.sync.aligned.m16n8k8.row.col.f32.tf32.tf32.f32 "
        "{%0,%1,%2,%3}, {%4,%5,%6,%7}, {%8,%9}, {%0,%1,%2,%3};"
        : "+f"(c[0]), "+f"(c[1]), "+f"(c[2]), "+f"(c[3])
        : "r"(a[0]), "r"(a[1]), "r"(a[2]), "r"(a[3]), "r"(b0), "r"(b1));
}

// =============== TF32 mma GEMM: C[M,768] = A[M,768] @ W[768,768] + b ===============
#define APAD 36
#define BPAD 136

__global__ void __launch_bounds__(256) gemm_mma(
    const float* __restrict__ A, const float* __restrict__ Wm,
    const float* __restrict__ bias, float* __restrict__ C) {
    __shared__ uint32_t As[128 * APAD];
    __shared__ uint32_t Bs[32 * BPAD];
    const int tid = threadIdx.x;
    const int warp = tid >> 5, lane = tid & 31;
    const int g = lane >> 2, tg = lane & 3;
    const int wm = (warp >> 2) * 64;
    const int wn = (warp & 3) * 32;
    const int m0 = blockIdx.y * 128;
    const int n0 = blockIdx.x * 128;

    float acc[4][4][4];
    #pragma unroll
    for (int mi = 0; mi < 4; ++mi)
        #pragma unroll
        for (int ni = 0; ni < 4; ++ni)
            #pragma unroll
            for (int c = 0; c < 4; ++c) acc[mi][ni][c] = 0.f;

    #pragma unroll 1
    for (int ch = 0; ch < 24; ++ch) {
        const int k0 = ch * 32;
        #pragma unroll
        for (int it = 0; it < 4; ++it) {
            int lin = tid + it * 256;
            int row = lin >> 3, f4 = lin & 7;
            float4 v = *(const float4*)(A + (size_t)(m0 + row) * HIDc + k0 + f4 * 4);
            uint32_t* dst = &As[row * APAD + f4 * 4];
            dst[0] = to_tf32(v.x); dst[1] = to_tf32(v.y);
            dst[2] = to_tf32(v.z); dst[3] = to_tf32(v.w);
        }
        #pragma unroll
        for (int it = 0; it < 16; ++it) {
            int lin = tid + it * 256;
            int kk = lin >> 7, nn = lin & 127;
            Bs[kk * BPAD + nn] = to_tf32(Wm[(size_t)(k0 + kk) * HIDc + n0 + nn]);
        }
        __syncthreads();

        #pragma unroll
        for (int ks = 0; ks < 32; ks += 8) {
            uint32_t af[4][4], bf[4][2];
            #pragma unroll
            for (int mi = 0; mi < 4; ++mi) {
                int mb = wm + mi * 16;
                af[mi][0] = As[(mb + g) * APAD + ks + tg];
                af[mi][1] = As[(mb + g + 8) * APAD + ks + tg];
                af[mi][2] = As[(mb + g) * APAD + ks + tg + 4];
                af[mi][3] = As[(mb + g + 8) * APAD + ks + tg + 4];
            }
            #pragma unroll
            for (int ni = 0; ni < 4; ++ni) {
                int nb = wn + ni * 8 + g;
                bf[ni][0] = Bs[(ks + tg) * BPAD + nb];
                bf[ni][1] = Bs[(ks + tg + 4) * BPAD + nb];
            }
            #pragma unroll
            for (int mi = 0; mi < 4; ++mi)
                #pragma unroll
                for (int ni = 0; ni < 4; ++ni)
                    mma8(acc[mi][ni], af[mi], bf[ni][0], bf[ni][1]);
        }
        __syncthreads();
    }

    #pragma unroll
    for (int mi = 0; mi < 4; ++mi) {
        #pragma unroll
        for (int ni = 0; ni < 4; ++ni) {
            int r0 = m0 + wm + mi * 16 + g;
            int cc = n0 + wn + ni * 8 + 2 * tg;
            float2 b2 = *(const float2*)(bias + cc);
            float2 v0 = make_float2(acc[mi][ni][0] + b2.x, acc[mi][ni][1] + b2.y);
            float2 v1 = make_float2(acc[mi][ni][2] + b2.x, acc[mi][ni][3] + b2.y);
            *(float2*)(C + (size_t)r0 * HIDc + cc) = v0;
            *(float2*)(C + (size_t)(r0 + 8) * HIDc + cc) = v1;
        }
    }
}

// ---------------- pack mask+id into one byte ----------------
__global__ void pack_l_kernel(const int* __restrict__ l2l_m, const int* __restrict__ l2l_i,
                              const int* __restrict__ l2g_m, const int* __restrict__ l2g_i) {
    int i = blockIdx.x * blockDim.x + threadIdx.x;
    const int nl = Bc*Lc*Wc;
    const int ng = Bc*Lc*Gc;
    if (i < nl) g_pl2l[i] = (unsigned char)((l2l_i[i] & 31) | (l2l_m[i] ? 0x80 : 0));
    if (i < ng) g_pl2g[i] = (unsigned char)((l2g_i[i] & 31) | (l2g_m[i] ? 0x80 : 0));
}

__global__ void pack_g_kernel(const int* __restrict__ gg_m, const int* __restrict__ gg_i,
                              const int* __restrict__ gl_m, const int* __restrict__ gl_i) {
    int i = blockIdx.x * blockDim.x + threadIdx.x;
    const int total = Bc*Gc*KTOTG;
    if (i >= total) return;
    int row = i / KTOTG, col = i % KTOTG;
    unsigned char v;
    if (col < Gc) { int idx = row*Gc + col;        v = (unsigned char)((gg_i[idx] & 31) | (gg_m[idx] ? 0x80 : 0)); }
    else          { int idx = row*Lc + (col - Gc); v = (unsigned char)((gl_i[idx] & 31) | (gl_m[idx] ? 0x80 : 0)); }
    g_pg[i] = v;
}

// ---------------- fp32 tiled SGEMM (small M only) ----------------
template<int TM, int TN, int MM, int MN>
__global__ void gemm_bias(const float* __restrict__ A, const float* __restrict__ Wm,
                          const float* __restrict__ bias, float* __restrict__ C, int M) {
    constexpr int TK = 16;
    constexpr int TX = TN / MN;
    constexpr int TY = TM / MM;
    constexpr int NTHR = TX * TY;
    __shared__ float As[TK][TM + 4];
    __shared__ float Bs[TK][TN];
    const int tid = threadIdx.x;
    const int tx = tid % TX, ty = tid / TX;
    const int n0 = blockIdx.x * TN;
    const int m0 = blockIdx.y * TM;

    float acc[MM][MN];
    #pragma unroll
    for (int i = 0; i < MM; ++i)
        #pragma unroll
        for (int j = 0; j < MN; ++j) acc[i][j] = 0.f;

    for (int k0 = 0; k0 < HIDc; k0 += TK) {
        constexpr int AITER = TM*TK/NTHR;
        #pragma unroll
        for (int q2 = 0; q2 < AITER; ++q2) {
            int i = tid + q2*NTHR;
            int m = i / TK, kk = i % TK;
            As[kk][m] = A[(size_t)(m0 + m)*HIDc + k0 + kk];
        }
        constexpr int BITER = TK*TN/NTHR;
        #pragma unroll
        for (int q2 = 0; q2 < BITER; ++q2) {
            int i = tid + q2*NTHR;
            int kk = i / TN, n = i % TN;
            Bs[kk][n] = Wm[(size_t)(k0 + kk)*HIDc + n0 + n];
        }
        __syncthreads();
        #pragma unroll
        for (int kk = 0; kk < TK; ++kk) {
            float a[MM], bb[MN];
            #pragma unroll
            for (int i = 0; i < MM; ++i) a[i] = As[kk][ty*MM + i];
            #pragma unroll
            for (int j = 0; j < MN; ++j) bb[j] = Bs[kk][tx*MN + j];
            #pragma unroll
            for (int i = 0; i < MM; ++i)
                #pragma unroll
                for (int j = 0; j < MN; ++j) acc[i][j] += a[i]*bb[j];
        }
        __syncthreads();
    }
    #pragma unroll
    for (int i = 0; i < MM; ++i) {
        size_t crow = (size_t)(m0 + ty*MM + i)*HIDc + n0 + tx*MN;
        #pragma unroll
        for (int j = 0; j < MN; ++j)
            C[crow + j] = acc[i][j] + bias[n0 + tx*MN + j];
    }
}

// =============== mma-based attention ===============
// smem layout (bytes): sQ/sP [128][68]u32 @0 (34816); sK [64][68]u32 @34816 (17408);
// sV [64][72]u32 @52224 (18432); sRel [128][33]f @70656 (16896). total 87552.
#define ATT_SMEM 87552
#define OFF_K 34816
#define OFF_V 52224
#define OFF_REL 70656

// ---------------- long-token attention (one CTA per b, block, head) ----------------
__global__ void __launch_bounds__(256) long_attn_mma(
    const float* __restrict__ rel_emb, const float* __restrict__ rel_bias) {
    extern __shared__ char sm[];
    uint32_t* sQ  = (uint32_t*)sm;              // reused as sP
    uint32_t* sK  = (uint32_t*)(sm + OFF_K);
    uint32_t* sV  = (uint32_t*)(sm + OFF_V);
    float*    sRel = (float*)(sm + OFF_REL);

    const int tid = threadIdx.x;
    const int warp = tid >> 5, lane = tid & 31;
    const int g = lane >> 2, tg = lane & 3;
    const int n = blockIdx.x, h = blockIdx.y, b = blockIdx.z;
    const int pr0 = warp * 16 + g, pr1 = pr0 + 8;
    const int t0 = n * BLKc;
    const int jbase = (n - 1) * BLKc;

    // stage Q (tf32)
    #pragma unroll
    for (int it = 0; it < 8; ++it) {
        int lin = tid + it * 256;          // 0..2047 float4 units
        int row = lin >> 4, f4 = lin & 15;
        float4 v = *(const float4*)(g_lq + (((size_t)b*Lc + t0 + row)*Hc + h)*Dc + f4*4);
        uint32_t* dst = &sQ[row * 68 + f4 * 4];
        dst[0] = to_tf32(v.x); dst[1] = to_tf32(v.y);
        dst[2] = to_tf32(v.z); dst[3] = to_tf32(v.w);
    }
    // stage rel_emb rows (32 x 64) into sK
    #pragma unroll
    for (int it = 0; it < 2; ++it) {
        int lin = tid + it * 256;          // 0..511 float4 units
        int r = lin >> 4, f4 = lin & 15;
        float4 v = *(const float4*)(rel_emb + ((size_t)r*Hc + h)*Dc + f4*4);
        uint32_t* dst = &sK[r * 68 + f4 * 4];
        dst[0] = to_tf32(v.x); dst[1] = to_tf32(v.y);
        dst[2] = to_tf32(v.z); dst[3] = to_tf32(v.w);
    }
    __syncthreads();

    // Q a-frags
    uint32_t qa[8][4];
    #pragma unroll
    for (int kf = 0; kf < 8; ++kf) {
        int k0 = kf * 8;
        qa[kf][0] = sQ[pr0 * 68 + k0 + tg];
        qa[kf][1] = sQ[pr1 * 68 + k0 + tg];
        qa[kf][2] = sQ[pr0 * 68 + k0 + tg + 4];
        qa[kf][3] = sQ[pr1 * 68 + k0 + tg + 4];
    }

    // rel scores: S_rel = Q @ R^T  (128 x 32)
    {
        float rc[4][4];
        #pragma unroll
        for (int nf = 0; nf < 4; ++nf)
            #pragma unroll
            for (int e = 0; e < 4; ++e) rc[nf][e] = 0.f;
        #pragma unroll
        for (int kf = 0; kf < 8; ++kf)
            #pragma unroll
            for (int nf = 0; nf < 4; ++nf) {
                uint32_t b0 = sK[(nf*8 + g) * 68 + kf*8 + tg];
                uint32_t b1 = sK[(nf*8 + g) * 68 + kf*8 + tg + 4];
                mma8(rc[nf], qa[kf], b0, b1);
            }
        #pragma unroll
        for (int nf = 0; nf < 4; ++nf) {
            int c = nf * 8 + 2 * tg;
            sRel[pr0*33 + c]     = rc[nf][0] + rel_bias[c*Hc + h];
            sRel[pr0*33 + c + 1] = rc[nf][1] + rel_bias[(c+1)*Hc + h];
            sRel[pr1*33 + c]     = rc[nf][2] + rel_bias[c*Hc + h];
            sRel[pr1*33 + c + 1] = rc[nf][3] + rel_bias[(c+1)*Hc + h];
        }
    }

    float accO[8][4];
    #pragma unroll
    for (int nf = 0; nf < 8; ++nf)
        #pragma unroll
        for (int e = 0; e < 4; ++e) accO[nf][e] = 0.f;
    float ls0 = 0.f, ls1 = 0.f;

    const unsigned char* prow0L = g_pl2l + (size_t)(b*Lc + t0 + pr0)*Wc;
    const unsigned char* prow1L = g_pl2l + (size_t)(b*Lc + t0 + pr1)*Wc;
    const unsigned char* prow0G = g_pl2g + (size_t)(b*Lc + t0 + pr0)*Gc;
    const unsigned char* prow1G = g_pl2g + (size_t)(b*Lc + t0 + pr1)*Gc;

    #pragma unroll 1
    for (int tile = 0; tile < 10; ++tile) {
        __syncthreads();   // previous tile fully consumed (also covers rel staging)
        if (tile < 6) {
            const int c0 = tile * 64;
            #pragma unroll
            for (int it = 0; it < 4; ++it) {
                int lin = tid + it * 256;      // 0..1023 float4 units
                int kk = lin >> 4, f4 = lin & 15;
                int j = jbase + c0 + kk;
                float4 kv = make_float4(0.f,0.f,0.f,0.f), vv = make_float4(0.f,0.f,0.f,0.f);
                if (j >= 0 && j < Lc) {
                    size_t off = (((size_t)b*Lc + j)*Hc + h)*Dc + f4*4;
                    kv = *(const float4*)(g_lk + off);
                    vv = *(const float4*)(g_lv + off);
                }
                uint32_t* dk = &sK[kk*68 + f4*4];
                dk[0]=to_tf32(kv.x); dk[1]=to_tf32(kv.y); dk[2]=to_tf32(kv.z); dk[3]=to_tf32(kv.w);
                uint32_t* dv = &sV[kk*72 + f4*4];
                dv[0]=to_tf32(vv.x); dv[1]=to_tf32(vv.y); dv[2]=to_tf32(vv.z); dv[3]=to_tf32(vv.w);
            }
        } else {
            const int g0 = (tile - 6) * 64;
            #pragma unroll
            for (int it = 0; it < 4; ++it) {
                int lin = tid + it * 256;
                int kk = lin >> 4, f4 = lin & 15;
                size_t off = (((size_t)b*Gc + g0 + kk)*Hc + h)*Dc + f4*4;
                float4 kv = *(const float4*)(g_gk + off);
                float4 vv = *(const float4*)(g_gv + off);
                uint32_t* dk = &sK[kk*68 + f4*4];
                dk[0]=to_tf32(kv.x); dk[1]=to_tf32(kv.y); dk[2]=to_tf32(kv.z); dk[3]=to_tf32(kv.w);
                uint32_t* dv = &sV[kk*72 + f4*4];
                dv[0]=to_tf32(vv.x); dv[1]=to_tf32(vv.y); dv[2]=to_tf32(vv.z); dv[3]=to_tf32(vv.w);
            }
        }
        __syncthreads();

        // S = Q @ K^T (this warp: 16 rows x 64 keys)
        float sc[8][4];
        #pragma unroll
        for (int nf = 0; nf < 8; ++nf)
            #pragma unroll
            for (int e = 0; e < 4; ++e) sc[nf][e] = 0.f;
        #pragma unroll
        for (int kf = 0; kf < 8; ++kf)
            #pragma unroll
            for (int nf = 0; nf < 8; ++nf) {
                uint32_t b0 = sK[(nf*8 + g) * 68 + kf*8 + tg];
                uint32_t b1 = sK[(nf*8 + g) * 68 + kf*8 + tg + 4];
                mma8(sc[nf], qa[kf], b0, b1);
            }

        // softmax (no-max) + mask + rel, write P to warp-private sP rows
        #pragma unroll
        for (int nf = 0; nf < 8; ++nf) {
            #pragma unroll
            for (int e = 0; e < 4; ++e) {
                const int pr = (e < 2) ? pr0 : pr1;
                const int cl = nf*8 + 2*tg + (e & 1);
                unsigned char byt; bool ok;
                if (tile < 6) {
                    int c = tile*64 + cl;
                    int r = c - pr - 1;
                    int j = jbase + c;
                    ok = (r >= 0) && (r < Wc) && (j >= 0) && (j < Lc);
                    byt = ok ? ((e < 2) ? prow0L : prow1L)[r >= 0 ? (r < Wc ? r : Wc-1) : 0] : (unsigned char)0;
                } else {
                    int idx = (tile - 6)*64 + cl;
                    byt = ((e < 2) ? prow0G : prow1G)[idx];
                    ok = true;
                }
                ok = ok && (byt & 0x80);
                float s = (sc[nf][e] + sRel[pr*33 + (byt & 31)]) * SCALEc;
                float p = ok ? __expf(s) : 0.f;
                uint32_t pt = to_tf32(p);
                p = __uint_as_float(pt);
                if (e < 2) ls0 += p; else ls1 += p;
                sQ[pr*68 + cl] = pt;   // sP
            }
        }
        __syncwarp();

        // O += P @ V  (A-frags from warp-private sP rows)
        #pragma unroll
        for (int kf = 0; kf < 8; ++kf) {
            uint32_t pa[4];
            pa[0] = sQ[pr0*68 + kf*8 + tg];
            pa[1] = sQ[pr1*68 + kf*8 + tg];
            pa[2] = sQ[pr0*68 + kf*8 + tg + 4];
            pa[3] = sQ[pr1*68 + kf*8 + tg + 4];
            #pragma unroll
            for (int nf = 0; nf < 8; ++nf) {
                uint32_t b0 = sV[(kf*8 + tg) * 72 + nf*8 + g];
                uint32_t b1 = sV[(kf*8 + tg + 4) * 72 + nf*8 + g];
                mma8(accO[nf], pa, b0, b1);
            }
        }
        __syncwarp();
    }

    // reduce row sums across the quad (lanes g*4 + tg)
    ls0 += __shfl_xor_sync(0xFFFFFFFF, ls0, 1);
    ls0 += __shfl_xor_sync(0xFFFFFFFF, ls0, 2);
    ls1 += __shfl_xor_sync(0xFFFFFFFF, ls1, 1);
    ls1 += __shfl_xor_sync(0xFFFFFFFF, ls1, 2);
    const float inv0 = 1.f / ls0, inv1 = 1.f / ls1;

    #pragma unroll
    for (int nf = 0; nf < 8; ++nf) {
        int c = nf*8 + 2*tg;
        float2 v0 = make_float2(accO[nf][0]*inv0, accO[nf][1]*inv0);
        float2 v1 = make_float2(accO[nf][2]*inv1, accO[nf][3]*inv1);
        *(float2*)(g_lctx + (((size_t)b*Lc + t0 + pr0)*Hc + h)*Dc + c) = v0;
        *(float2*)(g_lctx + (((size_t)b*Lc + t0 + pr1)*Hc + h)*Dc + c) = v1;
    }
}

// ---------------- global-token attention (split-K, partial outputs) ----------------
__global__ void __launch_bounds__(256) glob_attn_mma(
    const float* __restrict__ rel_emb, const float* __restrict__ rel_bias) {
    extern __shared__ char sm[];
    uint32_t* sQ  = (uint32_t*)sm;
    uint32_t* sK  = (uint32_t*)(sm + OFF_K);
    uint32_t* sV  = (uint32_t*)(sm + OFF_V);
    float*    sRel = (float*)(sm + OFF_REL);

    const int tid = threadIdx.x;
    const int warp = tid >> 5, lane = tid & 31;
    const int g = lane >> 2, tg = lane & 3;
    const int qt = blockIdx.x;        // 0..1
    const int split = blockIdx.y;     // 0..3
    const int bh = blockIdx.z;        // 0..23
    const int b = bh / Hc, h = bh % Hc;
    const int pr0 = warp * 16 + g, pr1 = pr0 + 8;
    const int q0 = qt * 128;

    // stage Q
    #pragma unroll
    for (int it = 0; it < 8; ++it) {
        int lin = tid + it * 256;
        int row = lin >> 4, f4 = lin & 15;
        float4 v = *(const float4*)(g_gq + (((size_t)b*Gc + q0 + row)*Hc + h)*Dc + f4*4);
        uint32_t* dst = &sQ[row * 68 + f4 * 4];
        dst[0] = to_tf32(v.x); dst[1] = to_tf32(v.y);
        dst[2] = to_tf32(v.z); dst[3] = to_tf32(v.w);
    }
    #pragma unroll
    for (int it = 0; it < 2; ++it) {
        int lin = tid + it * 256;
        int r = lin >> 4, f4 = lin & 15;
        float4 v = *(const float4*)(rel_emb + ((size_t)r*Hc + h)*Dc + f4*4);
        uint32_t* dst = &sK[r * 68 + f4 * 4];
        dst[0] = to_tf32(v.x); dst[1] = to_tf32(v.y);
        dst[2] = to_tf32(v.z); dst[3] = to_tf32(v.w);
    }
    __syncthreads();

    uint32_t qa[8][4];
    #pragma unroll
    for (int kf = 0; kf < 8; ++kf) {
        int k0 = kf * 8;
        qa[kf][0] = sQ[pr0 * 68 + k0 + tg];
        qa[kf][1] = sQ[pr1 * 68 + k0 + tg];
        qa[kf][2] = sQ[pr0 * 68 + k0 + tg + 4];
        qa[kf][3] = sQ[pr1 * 68 + k0 + tg + 4];
    }

    {
        float rc[4][4];
        #pragma unroll
        for (int nf = 0; nf < 4; ++nf)
            #pragma unroll
            for (int e = 0; e < 4; ++e) rc[nf][e] = 0.f;
        #pragma unroll
        for (int kf = 0; kf < 8; ++kf)
            #pragma unroll
            for (int nf = 0; nf < 4; ++nf) {
                uint32_t b0 = sK[(nf*8 + g) * 68 + kf*8 + tg];
                uint32_t b1 = sK[(nf*8 + g) * 68 + kf*8 + tg + 4];
                mma8(rc[nf], qa[kf], b0, b1);
            }
        #pragma unroll
        for (int nf = 0; nf < 4; ++nf) {
            int c = nf * 8 + 2 * tg;
            sRel[pr0*33 + c]     = rc[nf][0] + rel_bias[c*Hc + h];
            sRel[pr0*33 + c + 1] = rc[nf][1] + rel_bias[(c+1)*Hc + h];
            sRel[pr1*33 + c]     = rc[nf][2] + rel_bias[c*Hc + h];
            sRel[pr1*33 + c + 1] = rc[nf][3] + rel_bias[(c+1)*Hc + h];
        }
    }

    float accO[8][4];
    #pragma unroll
    for (int nf = 0; nf < 8; ++nf)
        #pragma unroll
        for (int e = 0; e < 4; ++e) accO[nf][e] = 0.f;
    float ls0 = 0.f, ls1 = 0.f;

    const unsigned char* prow0 = g_pg + (size_t)(b*Gc + q0 + pr0)*KTOTG;
    const unsigned char* prow1 = g_pg + (size_t)(b*Gc + q0 + pr1)*KTOTG;

    #pragma unroll 1
    for (int tt = 0; tt < 17; ++tt) {
        const int tile = split * 17 + tt;
        const int j0 = tile * 64;
        __syncthreads();
        #pragma unroll
        for (int it = 0; it < 4; ++it) {
            int lin = tid + it * 256;
            int kk = lin >> 4, f4 = lin & 15;
            int j = j0 + kk;
            size_t off;
            const float *kp, *vp;
            if (j < Gc) { off = (((size_t)b*Gc + j)*Hc + h)*Dc + f4*4;        kp = g_gk; vp = g_gv; }
            else        { off = (((size_t)b*Lc + (j - Gc))*Hc + h)*Dc + f4*4; kp = g_lk; vp = g_lv; }
            float4 kv = *(const float4*)(kp + off);
            float4 vv = *(const float4*)(vp + off);
            uint32_t* dk = &sK[kk*68 + f4*4];
            dk[0]=to_tf32(kv.x); dk[1]=to_tf32(kv.y); dk[2]=to_tf32(kv.z); dk[3]=to_tf32(kv.w);
            uint32_t* dv = &sV[kk*72 + f4*4];
            dv[0]=to_tf32(vv.x); dv[1]=to_tf32(vv.y); dv[2]=to_tf32(vv.z); dv[3]=to_tf32(vv.w);
        }
        __syncthreads();

        float sc[8][4];
        #pragma unroll
        for (int nf = 0; nf < 8; ++nf)
            #pragma unroll
            for (int e = 0; e < 4; ++e) sc[nf][e] = 0.f;
        #pragma unroll
        for (int kf = 0; kf < 8; ++kf)
            #pragma unroll
            for (int nf = 0; nf < 8; ++nf) {
                uint32_t b0 = sK[(nf*8 + g) * 68 + kf*8 + tg];
                uint32_t b1 = sK[(nf*8 + g) * 68 + kf*8 + tg + 4];
                mma8(sc[nf], qa[kf], b0, b1);
            }

        #pragma unroll
        for (int nf = 0; nf < 8; ++nf) {
            #pragma unroll
            for (int e = 0; e < 4; ++e) {
                const int pr = (e < 2) ? pr0 : pr1;
                const int cl = nf*8 + 2*tg + (e & 1);
                unsigned char byt = ((e < 2) ? prow0 : prow1)[j0 + cl];
                bool ok = (byt & 0x80) != 0;
                float s = (sc[nf][e] + sRel[pr*33 + (byt & 31)]) * SCALEc;
                float p = ok ? __expf(s) : 0.f;
                uint32_t pt = to_tf32(p);
                p = __uint_as_float(pt);
                if (e < 2) ls0 += p; else ls1 += p;
                sQ[pr*68 + cl] = pt;
            }
        }
        __syncwarp();

        #pragma unroll
        for (int kf = 0; kf < 8; ++kf) {
            uint32_t pa[4];
            pa[0] = sQ[pr0*68 + kf*8 + tg];
            pa[1] = sQ[pr1*68 + kf*8 + tg];
            pa[2] = sQ[pr0*68 + kf*8 + tg + 4];
            pa[3] = sQ[pr1*68 + kf*8 + tg + 4];
            #pragma unroll
            for (int nf = 0; nf < 8; ++nf) {
                uint32_t b0 = sV[(kf*8 + tg) * 72 + nf*8 + g];
                uint32_t b1 = sV[(kf*8 + tg + 4) * 72 + nf*8 + g];
                mma8(accO[nf], pa, b0, b1);
            }
        }
        __syncwarp();
    }

    ls0 += __shfl_xor_sync(0xFFFFFFFF, ls0, 1);
    ls0 += __shfl_xor_sync(0xFFFFFFFF, ls0, 2);
    ls1 += __shfl_xor_sync(0xFFFFFFFF, ls1, 1);
    ls1 += __shfl_xor_sync(0xFFFFFFFF, ls1, 2);

    const int pi = (bh * 2 + qt) * GSPLIT + split;
    float* pa = g_part_acc + (size_t)pi * 128 * 64;
    #pragma unroll
    for (int nf = 0; nf < 8; ++nf) {
        int c = nf*8 + 2*tg;
        *(float2*)(pa + pr0*64 + c) = make_float2(accO[nf][0], accO[nf][1]);
        *(float2*)(pa + pr1*64 + c) = make_float2(accO[nf][2], accO[nf][3]);
    }
    if (tg == 0) {
        g_part_l[pi*128 + pr0] = ls0;
        g_part_l[pi*128 + pr1] = ls1;
    }
}

__global__ void glob_combine2() {
    const int bq = blockIdx.x >> 7;        // (bh*2 + qt)
    const int row = blockIdx.x & 127;
    const int d = threadIdx.x;             // 0..63
    const int bh = bq >> 1, qt = bq & 1;
    const int b = bh / Hc, h = bh % Hc;
    const int qi = qt * 128 + row;
    float a = 0.f, l = 0.f;
    #pragma unroll
    for (int s = 0; s < GSPLIT; ++s) {
        int pi = bq * GSPLIT + s;
        a += g_part_acc[(size_t)pi*128*64 + row*64 + d];
        l += g_part_l[pi*128 + row];
    }
    g_gctx[(((size_t)b*Gc + qi)*Hc + h)*Dc + d] = a / l;
}

// ---------------- host launcher ----------------
extern "C" void kernel_launch(void* const* d_in, const int* in_sizes, int n_in,
                              void* d_out, int out_size) {
    (void)in_sizes; (void)n_in; (void)out_size;

    const float* long_input   = (const float*)d_in[0];
    const float* global_input = (const float*)d_in[1];
    const int* l2l_m = (const int*)d_in[2];
    const int* g2g_m = (const int*)d_in[3];
    const int* l2g_m = (const int*)d_in[4];
    const int* g2l_m = (const int*)d_in[5];
    const int* l2l_i = (const int*)d_in[6];
    const int* g2g_i = (const int*)d_in[7];
    const int* l2g_i = (const int*)d_in[8];
    const int* g2l_i = (const int*)d_in[9];
    const float* wq_long = (const float*)d_in[10];
    const float* bq_long = (const float*)d_in[11];
    const float* wk_long = (const float*)d_in[12];
    const float* bk_long = (const float*)d_in[13];
    const float* wv_long = (const float*)d_in[14];
    const float* bv_long = (const float*)d_in[15];
    const float* wq_glob = (const float*)d_in[16];
    const float* bq_glob = (const float*)d_in[17];
    const float* wk_glob = (const float*)d_in[18];
    const float* bk_glob = (const float*)d_in[19];
    const float* wv_glob = (const float*)d_in[20];
    const float* bv_glob = (const float*)d_in[21];
    const float* rel_emb_long  = (const float*)d_in[22];
    const float* rel_bias_long = (const float*)d_in[23];
    const float* rel_emb_glob  = (const float*)d_in[24];
    const float* rel_bias_glob = (const float*)d_in[25];
    const float* wo_long = (const float*)d_in[26];
    const float* bo_long = (const float*)d_in[27];
    const float* wo_glob = (const float*)d_in[28];
    const float* bo_glob = (const float*)d_in[29];

    float *lq, *lk, *lv, *gq, *gk, *gv, *lctx, *gctx;
    cudaGetSymbolAddress((void**)&lq,   g_lq);
    cudaGetSymbolAddress((void**)&lk,   g_lk);
    cudaGetSymbolAddress((void**)&lv,   g_lv);
    cudaGetSymbolAddress((void**)&gq,   g_gq);
    cudaGetSymbolAddress((void**)&gk,   g_gk);
    cudaGetSymbolAddress((void**)&gv,   g_gv);
    cudaGetSymbolAddress((void**)&lctx, g_lctx);
    cudaGetSymbolAddress((void**)&gctx, g_gctx);

    cudaFuncSetAttribute(long_attn_mma, cudaFuncAttributeMaxDynamicSharedMemorySize, ATT_SMEM);
    cudaFuncSetAttribute(glob_attn_mma, cudaFuncAttributeMaxDynamicSharedMemorySize, ATT_SMEM);

    // 1) pack mask+id bytes
    {
        int nmax = Bc*Lc*Gc;
        pack_l_kernel<<<(nmax + 255)/256, 256>>>(l2l_m, l2l_i, l2g_m, l2g_i);
        int ntot = Bc*Gc*KTOTG;
        pack_g_kernel<<<(ntot + 255)/256, 256>>>(g2g_m, g2g_i, g2l_m, g2l_i);
    }

    // 2) projections
    dim3 gbig(HIDc/128, (Bc*Lc)/128);
    dim3 gsm (HIDc/64,  (Bc*Gc)/64);
    gemm_mma<<<gbig, 256>>>(long_input, wq_long, bq_long, lq);
    gemm_mma<<<gbig, 256>>>(long_input, wk_long, bk_long, lk);
    gemm_mma<<<gbig, 256>>>(long_input, wv_long, bv_long, lv);
    gemm_bias<64,64,8,4><<<gsm, 128>>>(global_input, wq_glob, bq_glob, gq, Bc*Gc);
    gemm_bias<64,64,8,4><<<gsm, 128>>>(global_input, wk_glob, bk_glob, gk, Bc*Gc);
    gemm_bias<64,64,8,4><<<gsm, 128>>>(global_input, wv_glob, bv_glob, gv, Bc*Gc);

    // 3) long attention (mma)
    dim3 gla(Nc, Hc, Bc);
    long_attn_mma<<<gla, 256, ATT_SMEM>>>(rel_emb_long, rel_bias_long);

    // 4) global attention (mma, split-K) + combine
    dim3 gga(2, GSPLIT, Bc*Hc);
    glob_attn_mma<<<gga, 256, ATT_SMEM>>>(rel_emb_glob, rel_bias_glob);
    glob_combine2<<<Bc*Hc*2*128, 64>>>();

    // 5) output projections
    float* out_long = (float*)d_out;
    float* out_glob = out_long + (size_t)Bc*Lc*HIDc;
    gemm_mma<<<gbig, 256>>>(lctx, wo_long, bo_long, out_long);
    gemm_bias<64,64,8,4><<<gsm, 128>>>(gctx, wo_glob, bo_glob, out_glob, Bc*Gc);
}

// round 6
// speedup vs baseline: 2.2795x; 1.0273x over previous
#include <cuda_runtime.h>
#include <cuda_bf16.h>
#include <cstdint>

#define Bc 2
#define Lc 4096
#define Gc 256
#define HIDc 768
#define Hc 12
#define Dc 64
#define Wc 255
#define BLKc 128
#define Nc 32
#define Vc 32
#define KTOTG (Gc + Lc)   /* 4352 */
#define SCALEc 0.125f
#define GSPLIT 4          /* key splits for global attention */

// ---------------- device scratch (no allocations allowed) ----------------
__device__ float g_lq[Bc*Lc*HIDc];
__device__ float g_lk[Bc*Lc*HIDc];
__device__ float g_lv[Bc*Lc*HIDc];
__device__ float g_gq[Bc*Gc*HIDc];
__device__ float g_gk[Bc*Gc*HIDc];
__device__ float g_gv[Bc*Gc*HIDc];
__device__ float g_lctx[Bc*Lc*HIDc];
__device__ float g_gctx[Bc*Gc*HIDc];
__device__ unsigned char g_pl2l[Bc*Lc*Wc];
__device__ unsigned char g_pl2g[Bc*Lc*Gc];
__device__ unsigned char g_pg[Bc*Gc*KTOTG];
__device__ float g_part_acc[(size_t)Bc*Hc*2*GSPLIT*128*64];
__device__ float g_part_l[Bc*Hc*2*GSPLIT*128];

// ---------------- helpers ----------------
__device__ __forceinline__ uint32_t to_tf32(float f) {
    uint32_t r;
    asm("cvt.rna.tf32.f32 %0, %1;" : "=r"(r) : "f"(f));
    return r;
}
__device__ __forceinline__ void mma8(float* c, const uint32_t* a, uint32_t b0, uint32_t b1) {
    asm volatile("mma.sync.aligned.m16n8k8.row.col.f32.tf32.tf32.f32 "
        "{%0,%1,%2,%3}, {%4,%5,%6,%7}, {%8,%9}, {%0,%1,%2,%3};"
        : "+f"(c[0]), "+f"(c[1]), "+f"(c[2]), "+f"(c[3])
        : "r"(a[0]), "r"(a[1]), "r"(a[2]), "r"(a[3]), "r"(b0), "r"(b1));
}

// =============== TF32 mma GEMM (pipelined, double-buffered) ===============
// C[M,768] = A[M,768] @ W[768,768] + b.  CTA tile 128x128, K-chunk 32.
#define APAD 36
#define BPAD 136
#define ABUF (128 * APAD)          /* 4608 u32 */
#define BBUF (32 * BPAD)           /* 4352 u32 */
#define GEMM_SMEM ((2*ABUF + 2*BBUF) * 4)   /* 71680 bytes */

__global__ void __launch_bounds__(256) gemm_mma(
    const float* __restrict__ A, const float* __restrict__ Wm,
    const float* __restrict__ bias, float* __restrict__ C) {
    extern __shared__ uint32_t smu[];
    uint32_t* As[2] = { smu, smu + ABUF };
    uint32_t* Bs[2] = { smu + 2*ABUF, smu + 2*ABUF + BBUF };

    const int tid = threadIdx.x;
    const int warp = tid >> 5, lane = tid & 31;
    const int g = lane >> 2, tg = lane & 3;
    const int wm = (warp >> 2) * 64;
    const int wn = (warp & 3) * 32;
    const int m0 = blockIdx.y * 128;
    const int n0 = blockIdx.x * 128;

    // per-thread staging addresses
    const int arow = tid >> 1;                 // A: 2 thr/row? no: see below
    (void)arow;

    float acc[4][4][4];
    #pragma unroll
    for (int mi = 0; mi < 4; ++mi)
        #pragma unroll
        for (int ni = 0; ni < 4; ++ni)
            #pragma unroll
            for (int c = 0; c < 4; ++c) acc[mi][ni][c] = 0.f;

    float4 ra[4];      // A: 4 float4 per thread (1024 float4 total)
    float4 rb[4];      // B: 4 float4 per thread (1024 float4 total)

    auto load_regs = [&](int ch) {
        const int k0 = ch * 32;
        #pragma unroll
        for (int it = 0; it < 4; ++it) {
            int lin = tid + it * 256;           // 0..1023
            int row = lin >> 3, f4 = lin & 7;
            ra[it] = *(const float4*)(A + (size_t)(m0 + row) * HIDc + k0 + f4 * 4);
        }
        #pragma unroll
        for (int it = 0; it < 4; ++it) {
            int lin = tid + it * 256;           // 0..1023
            int kk = lin >> 5, c4 = lin & 31;
            rb[it] = *(const float4*)(Wm + (size_t)(k0 + kk) * HIDc + n0 + c4 * 4);
        }
    };
    auto store_smem = [&](int buf) {
        #pragma unroll
        for (int it = 0; it < 4; ++it) {
            int lin = tid + it * 256;
            int row = lin >> 3, f4 = lin & 7;
            uint32_t* dst = &As[buf][row * APAD + f4 * 4];
            dst[0] = to_tf32(ra[it].x); dst[1] = to_tf32(ra[it].y);
            dst[2] = to_tf32(ra[it].z); dst[3] = to_tf32(ra[it].w);
        }
        #pragma unroll
        for (int it = 0; it < 4; ++it) {
            int lin = tid + it * 256;
            int kk = lin >> 5, c4 = lin & 31;
            uint32_t* dst = &Bs[buf][kk * BPAD + c4 * 4];
            dst[0] = to_tf32(rb[it].x); dst[1] = to_tf32(rb[it].y);
            dst[2] = to_tf32(rb[it].z); dst[3] = to_tf32(rb[it].w);
        }
    };

    load_regs(0);
    store_smem(0);

    #pragma unroll 1
    for (int ch = 0; ch < 24; ++ch) {
        const int buf = ch & 1;
        if (ch < 23) load_regs(ch + 1);
        __syncthreads();
        #pragma unroll
        for (int ks = 0; ks < 32; ks += 8) {
            uint32_t af[4][4], bf[4][2];
            #pragma unroll
            for (int mi = 0; mi < 4; ++mi) {
                int mb = wm + mi * 16;
                af[mi][0] = As[buf][(mb + g) * APAD + ks + tg];
                af[mi][1] = As[buf][(mb + g + 8) * APAD + ks + tg];
                af[mi][2] = As[buf][(mb + g) * APAD + ks + tg + 4];
                af[mi][3] = As[buf][(mb + g + 8) * APAD + ks + tg + 4];
            }
            #pragma unroll
            for (int ni = 0; ni < 4; ++ni) {
                int nb = wn + ni * 8 + g;
                bf[ni][0] = Bs[buf][(ks + tg) * BPAD + nb];
                bf[ni][1] = Bs[buf][(ks + tg + 4) * BPAD + nb];
            }
            #pragma unroll
            for (int mi = 0; mi < 4; ++mi)
                #pragma unroll
                for (int ni = 0; ni < 4; ++ni)
                    mma8(acc[mi][ni], af[mi], bf[ni][0], bf[ni][1]);
        }
        if (ch < 23) store_smem(buf ^ 1);
    }

    #pragma unroll
    for (int mi = 0; mi < 4; ++mi) {
        #pragma unroll
        for (int ni = 0; ni < 4; ++ni) {
            int r0 = m0 + wm + mi * 16 + g;
            int cc = n0 + wn + ni * 8 + 2 * tg;
            float2 b2 = *(const float2*)(bias + cc);
            float2 v0 = make_float2(acc[mi][ni][0] + b2.x, acc[mi][ni][1] + b2.y);
            float2 v1 = make_float2(acc[mi][ni][2] + b2.x, acc[mi][ni][3] + b2.y);
            *(float2*)(C + (size_t)r0 * HIDc + cc) = v0;
            *(float2*)(C + (size_t)(r0 + 8) * HIDc + cc) = v1;
        }
    }
}

// ---------------- pack mask+id into one byte ----------------
__global__ void pack_l_kernel(const int* __restrict__ l2l_m, const int* __restrict__ l2l_i,
                              const int* __restrict__ l2g_m, const int* __restrict__ l2g_i) {
    int i = blockIdx.x * blockDim.x + threadIdx.x;
    const int nl = Bc*Lc*Wc;
    const int ng = Bc*Lc*Gc;
    if (i < nl) g_pl2l[i] = (unsigned char)((l2l_i[i] & 31) | (l2l_m[i] ? 0x80 : 0));
    if (i < ng) g_pl2g[i] = (unsigned char)((l2g_i[i] & 31) | (l2g_m[i] ? 0x80 : 0));
}

__global__ void pack_g_kernel(const int* __restrict__ gg_m, const int* __restrict__ gg_i,
                              const int* __restrict__ gl_m, const int* __restrict__ gl_i) {
    int i = blockIdx.x * blockDim.x + threadIdx.x;
    const int total = Bc*Gc*KTOTG;
    if (i >= total) return;
    int row = i / KTOTG, col = i % KTOTG;
    unsigned char v;
    if (col < Gc) { int idx = row*Gc + col;        v = (unsigned char)((gg_i[idx] & 31) | (gg_m[idx] ? 0x80 : 0)); }
    else          { int idx = row*Lc + (col - Gc); v = (unsigned char)((gl_i[idx] & 31) | (gl_m[idx] ? 0x80 : 0)); }
    g_pg[i] = v;
}

// ---------------- fp32 tiled SGEMM (small M only) ----------------
template<int TM, int TN, int MM, int MN>
__global__ void gemm_bias(const float* __restrict__ A, const float* __restrict__ Wm,
                          const float* __restrict__ bias, float* __restrict__ C, int M) {
    constexpr int TK = 16;
    constexpr int TX = TN / MN;
    constexpr int TY = TM / MM;
    constexpr int NTHR = TX * TY;
    __shared__ float As[TK][TM + 4];
    __shared__ float Bs[TK][TN];
    const int tid = threadIdx.x;
    const int tx = tid % TX, ty = tid / TX;
    const int n0 = blockIdx.x * TN;
    const int m0 = blockIdx.y * TM;

    float acc[MM][MN];
    #pragma unroll
    for (int i = 0; i < MM; ++i)
        #pragma unroll
        for (int j = 0; j < MN; ++j) acc[i][j] = 0.f;

    for (int k0 = 0; k0 < HIDc; k0 += TK) {
        constexpr int AITER = TM*TK/NTHR;
        #pragma unroll
        for (int q2 = 0; q2 < AITER; ++q2) {
            int i = tid + q2*NTHR;
            int m = i / TK, kk = i % TK;
            As[kk][m] = A[(size_t)(m0 + m)*HIDc + k0 + kk];
        }
        constexpr int BITER = TK*TN/NTHR;
        #pragma unroll
        for (int q2 = 0; q2 < BITER; ++q2) {
            int i = tid + q2*NTHR;
            int kk = i / TN, n = i % TN;
            Bs[kk][n] = Wm[(size_t)(k0 + kk)*HIDc + n0 + n];
        }
        __syncthreads();
        #pragma unroll
        for (int kk = 0; kk < TK; ++kk) {
            float a[MM], bb[MN];
            #pragma unroll
            for (int i = 0; i < MM; ++i) a[i] = As[kk][ty*MM + i];
            #pragma unroll
            for (int j = 0; j < MN; ++j) bb[j] = Bs[kk][tx*MN + j];
            #pragma unroll
            for (int i = 0; i < MM; ++i)
                #pragma unroll
                for (int j = 0; j < MN; ++j) acc[i][j] += a[i]*bb[j];
        }
        __syncthreads();
    }
    #pragma unroll
    for (int i = 0; i < MM; ++i) {
        size_t crow = (size_t)(m0 + ty*MM + i)*HIDc + n0 + tx*MN;
        #pragma unroll
        for (int j = 0; j < MN; ++j)
            C[crow + j] = acc[i][j] + bias[n0 + tx*MN + j];
    }
}

// =============== mma-based attention ===============
#define ATT_SMEM 87552
#define OFF_K 34816
#define OFF_V 52224
#define OFF_REL 70656

// ---------------- long-token attention (one CTA per b, block, head) ----------------
__global__ void __launch_bounds__(256) long_attn_mma(
    const float* __restrict__ rel_emb, const float* __restrict__ rel_bias) {
    extern __shared__ char sm[];
    uint32_t* sQ  = (uint32_t*)sm;              // reused as sP
    uint32_t* sK  = (uint32_t*)(sm + OFF_K);
    uint32_t* sV  = (uint32_t*)(sm + OFF_V);
    float*    sRel = (float*)(sm + OFF_REL);

    const int tid = threadIdx.x;
    const int warp = tid >> 5, lane = tid & 31;
    const int g = lane >> 2, tg = lane & 3;
    const int n = blockIdx.x, h = blockIdx.y, b = blockIdx.z;
    const int pr0 = warp * 16 + g, pr1 = pr0 + 8;
    const int t0 = n * BLKc;
    const int jbase = (n - 1) * BLKc;

    #pragma unroll
    for (int it = 0; it < 8; ++it) {
        int lin = tid + it * 256;
        int row = lin >> 4, f4 = lin & 15;
        float4 v = *(const float4*)(g_lq + (((size_t)b*Lc + t0 + row)*Hc + h)*Dc + f4*4);
        uint32_t* dst = &sQ[row * 68 + f4 * 4];
        dst[0] = to_tf32(v.x); dst[1] = to_tf32(v.y);
        dst[2] = to_tf32(v.z); dst[3] = to_tf32(v.w);
    }
    #pragma unroll
    for (int it = 0; it < 2; ++it) {
        int lin = tid + it * 256;
        int r = lin >> 4, f4 = lin & 15;
        float4 v = *(const float4*)(rel_emb + ((size_t)r*Hc + h)*Dc + f4*4);
        uint32_t* dst = &sK[r * 68 + f4 * 4];
        dst[0] = to_tf32(v.x); dst[1] = to_tf32(v.y);
        dst[2] = to_tf32(v.z); dst[3] = to_tf32(v.w);
    }
    __syncthreads();

    uint32_t qa[8][4];
    #pragma unroll
    for (int kf = 0; kf < 8; ++kf) {
        int k0 = kf * 8;
        qa[kf][0] = sQ[pr0 * 68 + k0 + tg];
        qa[kf][1] = sQ[pr1 * 68 + k0 + tg];
        qa[kf][2] = sQ[pr0 * 68 + k0 + tg + 4];
        qa[kf][3] = sQ[pr1 * 68 + k0 + tg + 4];
    }

    {
        float rc[4][4];
        #pragma unroll
        for (int nf = 0; nf < 4; ++nf)
            #pragma unroll
            for (int e = 0; e < 4; ++e) rc[nf][e] = 0.f;
        #pragma unroll
        for (int kf = 0; kf < 8; ++kf)
            #pragma unroll
            for (int nf = 0; nf < 4; ++nf) {
                uint32_t b0 = sK[(nf*8 + g) * 68 + kf*8 + tg];
                uint32_t b1 = sK[(nf*8 + g) * 68 + kf*8 + tg + 4];
                mma8(rc[nf], qa[kf], b0, b1);
            }
        #pragma unroll
        for (int nf = 0; nf < 4; ++nf) {
            int c = nf * 8 + 2 * tg;
            sRel[pr0*33 + c]     = rc[nf][0] + rel_bias[c*Hc + h];
            sRel[pr0*33 + c + 1] = rc[nf][1] + rel_bias[(c+1)*Hc + h];
            sRel[pr1*33 + c]     = rc[nf][2] + rel_bias[c*Hc + h];
            sRel[pr1*33 + c + 1] = rc[nf][3] + rel_bias[(c+1)*Hc + h];
        }
    }

    float accO[8][4];
    #pragma unroll
    for (int nf = 0; nf < 8; ++nf)
        #pragma unroll
        for (int e = 0; e < 4; ++e) accO[nf][e] = 0.f;
    float ls0 = 0.f, ls1 = 0.f;

    const unsigned char* prow0L = g_pl2l + (size_t)(b*Lc + t0 + pr0)*Wc;
    const unsigned char* prow1L = g_pl2l + (size_t)(b*Lc + t0 + pr1)*Wc;
    const unsigned char* prow0G = g_pl2g + (size_t)(b*Lc + t0 + pr0)*Gc;
    const unsigned char* prow1G = g_pl2g + (size_t)(b*Lc + t0 + pr1)*Gc;

    #pragma unroll 1
    for (int tile = 0; tile < 10; ++tile) {
        __syncthreads();
        if (tile < 6) {
            const int c0 = tile * 64;
            #pragma unroll
            for (int it = 0; it < 4; ++it) {
                int lin = tid + it * 256;
                int kk = lin >> 4, f4 = lin & 15;
                int j = jbase + c0 + kk;
                float4 kv = make_float4(0.f,0.f,0.f,0.f), vv = make_float4(0.f,0.f,0.f,0.f);
                if (j >= 0 && j < Lc) {
                    size_t off = (((size_t)b*Lc + j)*Hc + h)*Dc + f4*4;
                    kv = *(const float4*)(g_lk + off);
                    vv = *(const float4*)(g_lv + off);
                }
                uint32_t* dk = &sK[kk*68 + f4*4];
                dk[0]=to_tf32(kv.x); dk[1]=to_tf32(kv.y); dk[2]=to_tf32(kv.z); dk[3]=to_tf32(kv.w);
                uint32_t* dv = &sV[kk*72 + f4*4];
                dv[0]=to_tf32(vv.x); dv[1]=to_tf32(vv.y); dv[2]=to_tf32(vv.z); dv[3]=to_tf32(vv.w);
            }
        } else {
            const int g0 = (tile - 6) * 64;
            #pragma unroll
            for (int it = 0; it < 4; ++it) {
                int lin = tid + it * 256;
                int kk = lin >> 4, f4 = lin & 15;
                size_t off = (((size_t)b*Gc + g0 + kk)*Hc + h)*Dc + f4*4;
                float4 kv = *(const float4*)(g_gk + off);
                float4 vv = *(const float4*)(g_gv + off);
                uint32_t* dk = &sK[kk*68 + f4*4];
                dk[0]=to_tf32(kv.x); dk[1]=to_tf32(kv.y); dk[2]=to_tf32(kv.z); dk[3]=to_tf32(kv.w);
                uint32_t* dv = &sV[kk*72 + f4*4];
                dv[0]=to_tf32(vv.x); dv[1]=to_tf32(vv.y); dv[2]=to_tf32(vv.z); dv[3]=to_tf32(vv.w);
            }
        }
        __syncthreads();

        float sc[8][4];
        #pragma unroll
        for (int nf = 0; nf < 8; ++nf)
            #pragma unroll
            for (int e = 0; e < 4; ++e) sc[nf][e] = 0.f;
        #pragma unroll
        for (int kf = 0; kf < 8; ++kf)
            #pragma unroll
            for (int nf = 0; nf < 8; ++nf) {
                uint32_t b0 = sK[(nf*8 + g) * 68 + kf*8 + tg];
                uint32_t b1 = sK[(nf*8 + g) * 68 + kf*8 + tg + 4];
                mma8(sc[nf], qa[kf], b0, b1);
            }

        #pragma unroll
        for (int nf = 0; nf < 8; ++nf) {
            #pragma unroll
            for (int e = 0; e < 4; ++e) {
                const int pr = (e < 2) ? pr0 : pr1;
                const int cl = nf*8 + 2*tg + (e & 1);
                unsigned char byt; bool ok;
                if (tile < 6) {
                    int c = tile*64 + cl;
                    int r = c - pr - 1;
                    int j = jbase + c;
                    ok = (r >= 0) && (r < Wc) && (j >= 0) && (j < Lc);
                    byt = ok ? ((e < 2) ? prow0L : prow1L)[r >= 0 ? (r < Wc ? r : Wc-1) : 0] : (unsigned char)0;
                } else {
                    int idx = (tile - 6)*64 + cl;
                    byt = ((e < 2) ? prow0G : prow1G)[idx];
                    ok = true;
                }
                ok = ok && (byt & 0x80);
                float s = (sc[nf][e] + sRel[pr*33 + (byt & 31)]) * SCALEc;
                float p = ok ? __expf(s) : 0.f;
                uint32_t pt = to_tf32(p);
                p = __uint_as_float(pt);
                if (e < 2) ls0 += p; else ls1 += p;
                sQ[pr*68 + cl] = pt;
            }
        }
        __syncwarp();

        #pragma unroll
        for (int kf = 0; kf < 8; ++kf) {
            uint32_t pa[4];
            pa[0] = sQ[pr0*68 + kf*8 + tg];
            pa[1] = sQ[pr1*68 + kf*8 + tg];
            pa[2] = sQ[pr0*68 + kf*8 + tg + 4];
            pa[3] = sQ[pr1*68 + kf*8 + tg + 4];
            #pragma unroll
            for (int nf = 0; nf < 8; ++nf) {
                uint32_t b0 = sV[(kf*8 + tg) * 72 + nf*8 + g];
                uint32_t b1 = sV[(kf*8 + tg + 4) * 72 + nf*8 + g];
                mma8(accO[nf], pa, b0, b1);
            }
        }
        __syncwarp();
    }

    ls0 += __shfl_xor_sync(0xFFFFFFFF, ls0, 1);
    ls0 += __shfl_xor_sync(0xFFFFFFFF, ls0, 2);
    ls1 += __shfl_xor_sync(0xFFFFFFFF, ls1, 1);
    ls1 += __shfl_xor_sync(0xFFFFFFFF, ls1, 2);
    const float inv0 = 1.f / ls0, inv1 = 1.f / ls1;

    #pragma unroll
    for (int nf = 0; nf < 8; ++nf) {
        int c = nf*8 + 2*tg;
        float2 v0 = make_float2(accO[nf][0]*inv0, accO[nf][1]*inv0);
        float2 v1 = make_float2(accO[nf][2]*inv1, accO[nf][3]*inv1);
        *(float2*)(g_lctx + (((size_t)b*Lc + t0 + pr0)*Hc + h)*Dc + c) = v0;
        *(float2*)(g_lctx + (((size_t)b*Lc + t0 + pr1)*Hc + h)*Dc + c) = v1;
    }
}

// ---------------- global-token attention (split-K, partial outputs) ----------------
__global__ void __launch_bounds__(256) glob_attn_mma(
    const float* __restrict__ rel_emb, const float* __restrict__ rel_bias) {
    extern __shared__ char sm[];
    uint32_t* sQ  = (uint32_t*)sm;
    uint32_t* sK  = (uint32_t*)(sm + OFF_K);
    uint32_t* sV  = (uint32_t*)(sm + OFF_V);
    float*    sRel = (float*)(sm + OFF_REL);

    const int tid = threadIdx.x;
    const int warp = tid >> 5, lane = tid & 31;
    const int g = lane >> 2, tg = lane & 3;
    const int qt = blockIdx.x;
    const int split = blockIdx.y;
    const int bh = blockIdx.z;
    const int b = bh / Hc, h = bh % Hc;
    const int pr0 = warp * 16 + g, pr1 = pr0 + 8;
    const int q0 = qt * 128;

    #pragma unroll
    for (int it = 0; it < 8; ++it) {
        int lin = tid + it * 256;
        int row = lin >> 4, f4 = lin & 15;
        float4 v = *(const float4*)(g_gq + (((size_t)b*Gc + q0 + row)*Hc + h)*Dc + f4*4);
        uint32_t* dst = &sQ[row * 68 + f4 * 4];
        dst[0] = to_tf32(v.x); dst[1] = to_tf32(v.y);
        dst[2] = to_tf32(v.z); dst[3] = to_tf32(v.w);
    }
    #pragma unroll
    for (int it = 0; it < 2; ++it) {
        int lin = tid + it * 256;
        int r = lin >> 4, f4 = lin & 15;
        float4 v = *(const float4*)(rel_emb + ((size_t)r*Hc + h)*Dc + f4*4);
        uint32_t* dst = &sK[r * 68 + f4 * 4];
        dst[0] = to_tf32(v.x); dst[1] = to_tf32(v.y);
        dst[2] = to_tf32(v.z); dst[3] = to_tf32(v.w);
    }
    __syncthreads();

    uint32_t qa[8][4];
    #pragma unroll
    for (int kf = 0; kf < 8; ++kf) {
        int k0 = kf * 8;
        qa[kf][0] = sQ[pr0 * 68 + k0 + tg];
        qa[kf][1] = sQ[pr1 * 68 + k0 + tg];
        qa[kf][2] = sQ[pr0 * 68 + k0 + tg + 4];
        qa[kf][3] = sQ[pr1 * 68 + k0 + tg + 4];
    }

    {
        float rc[4][4];
        #pragma unroll
        for (int nf = 0; nf < 4; ++nf)
            #pragma unroll
            for (int e = 0; e < 4; ++e) rc[nf][e] = 0.f;
        #pragma unroll
        for (int kf = 0; kf < 8; ++kf)
            #pragma unroll
            for (int nf = 0; nf < 4; ++nf) {
                uint32_t b0 = sK[(nf*8 + g) * 68 + kf*8 + tg];
                uint32_t b1 = sK[(nf*8 + g) * 68 + kf*8 + tg + 4];
                mma8(rc[nf], qa[kf], b0, b1);
            }
        #pragma unroll
        for (int nf = 0; nf < 4; ++nf) {
            int c = nf * 8 + 2 * tg;
            sRel[pr0*33 + c]     = rc[nf][0] + rel_bias[c*Hc + h];
            sRel[pr0*33 + c + 1] = rc[nf][1] + rel_bias[(c+1)*Hc + h];
            sRel[pr1*33 + c]     = rc[nf][2] + rel_bias[c*Hc + h];
            sRel[pr1*33 + c + 1] = rc[nf][3] + rel_bias[(c+1)*Hc + h];
        }
    }

    float accO[8][4];
    #pragma unroll
    for (int nf = 0; nf < 8; ++nf)
        #pragma unroll
        for (int e = 0; e < 4; ++e) accO[nf][e] = 0.f;
    float ls0 = 0.f, ls1 = 0.f;

    const unsigned char* prow0 = g_pg + (size_t)(b*Gc + q0 + pr0)*KTOTG;
    const unsigned char* prow1 = g_pg + (size_t)(b*Gc + q0 + pr1)*KTOTG;

    #pragma unroll 1
    for (int tt = 0; tt < 17; ++tt) {
        const int tile = split * 17 + tt;
        const int j0 = tile * 64;
        __syncthreads();
        #pragma unroll
        for (int it = 0; it < 4; ++it) {
            int lin = tid + it * 256;
            int kk = lin >> 4, f4 = lin & 15;
            int j = j0 + kk;
            size_t off;
            const float *kp, *vp;
            if (j < Gc) { off = (((size_t)b*Gc + j)*Hc + h)*Dc + f4*4;        kp = g_gk; vp = g_gv; }
            else        { off = (((size_t)b*Lc + (j - Gc))*Hc + h)*Dc + f4*4; kp = g_lk; vp = g_lv; }
            float4 kv = *(const float4*)(kp + off);
            float4 vv = *(const float4*)(vp + off);
            uint32_t* dk = &sK[kk*68 + f4*4];
            dk[0]=to_tf32(kv.x); dk[1]=to_tf32(kv.y); dk[2]=to_tf32(kv.z); dk[3]=to_tf32(kv.w);
            uint32_t* dv = &sV[kk*72 + f4*4];
            dv[0]=to_tf32(vv.x); dv[1]=to_tf32(vv.y); dv[2]=to_tf32(vv.z); dv[3]=to_tf32(vv.w);
        }
        __syncthreads();

        float sc[8][4];
        #pragma unroll
        for (int nf = 0; nf < 8; ++nf)
            #pragma unroll
            for (int e = 0; e < 4; ++e) sc[nf][e] = 0.f;
        #pragma unroll
        for (int kf = 0; kf < 8; ++kf)
            #pragma unroll
            for (int nf = 0; nf < 8; ++nf) {
                uint32_t b0 = sK[(nf*8 + g) * 68 + kf*8 + tg];
                uint32_t b1 = sK[(nf*8 + g) * 68 + kf*8 + tg + 4];
                mma8(sc[nf], qa[kf], b0, b1);
            }

        #pragma unroll
        for (int nf = 0; nf < 8; ++nf) {
            #pragma unroll
            for (int e = 0; e < 4; ++e) {
                const int pr = (e < 2) ? pr0 : pr1;
                const int cl = nf*8 + 2*tg + (e & 1);
                unsigned char byt = ((e < 2) ? prow0 : prow1)[j0 + cl];
                bool ok = (byt & 0x80) != 0;
                float s = (sc[nf][e] + sRel[pr*33 + (byt & 31)]) * SCALEc;
                float p = ok ? __expf(s) : 0.f;
                uint32_t pt = to_tf32(p);
                p = __uint_as_float(pt);
                if (e < 2) ls0 += p; else ls1 += p;
                sQ[pr*68 + cl] = pt;
            }
        }
        __syncwarp();

        #pragma unroll
        for (int kf = 0; kf < 8; ++kf) {
            uint32_t pa[4];
            pa[0] = sQ[pr0*68 + kf*8 + tg];
            pa[1] = sQ[pr1*68 + kf*8 + tg];
            pa[2] = sQ[pr0*68 + kf*8 + tg + 4];
            pa[3] = sQ[pr1*68 + kf*8 + tg + 4];
            #pragma unroll
            for (int nf = 0; nf < 8; ++nf) {
                uint32_t b0 = sV[(kf*8 + tg) * 72 + nf*8 + g];
                uint32_t b1 = sV[(kf*8 + tg + 4) * 72 + nf*8 + g];
                mma8(accO[nf], pa, b0, b1);
            }
        }
        __syncwarp();
    }

    ls0 += __shfl_xor_sync(0xFFFFFFFF, ls0, 1);
    ls0 += __shfl_xor_sync(0xFFFFFFFF, ls0, 2);
    ls1 += __shfl_xor_sync(0xFFFFFFFF, ls1, 1);
    ls1 += __shfl_xor_sync(0xFFFFFFFF, ls1, 2);

    const int pi = (bh * 2 + qt) * GSPLIT + split;
    float* pa = g_part_acc + (size_t)pi * 128 * 64;
    #pragma unroll
    for (int nf = 0; nf < 8; ++nf) {
        int c = nf*8 + 2*tg;
        *(float2*)(pa + pr0*64 + c) = make_float2(accO[nf][0], accO[nf][1]);
        *(float2*)(pa + pr1*64 + c) = make_float2(accO[nf][2], accO[nf][3]);
    }
    if (tg == 0) {
        g_part_l[pi*128 + pr0] = ls0;
        g_part_l[pi*128 + pr1] = ls1;
    }
}

__global__ void glob_combine2() {
    const int bq = blockIdx.x >> 7;
    const int row = blockIdx.x & 127;
    const int d = threadIdx.x;
    const int bh = bq >> 1, qt = bq & 1;
    const int b = bh / Hc, h = bh % Hc;
    const int qi = qt * 128 + row;
    float a = 0.f, l = 0.f;
    #pragma unroll
    for (int s = 0; s < GSPLIT; ++s) {
        int pi = bq * GSPLIT + s;
        a += g_part_acc[(size_t)pi*128*64 + row*64 + d];
        l += g_part_l[pi*128 + row];
    }
    g_gctx[(((size_t)b*Gc + qi)*Hc + h)*Dc + d] = a / l;
}

// ---------------- host launcher ----------------
extern "C" void kernel_launch(void* const* d_in, const int* in_sizes, int n_in,
                              void* d_out, int out_size) {
    (void)in_sizes; (void)n_in; (void)out_size;

    const float* long_input   = (const float*)d_in[0];
    const float* global_input = (const float*)d_in[1];
    const int* l2l_m = (const int*)d_in[2];
    const int* g2g_m = (const int*)d_in[3];
    const int* l2g_m = (const int*)d_in[4];
    const int* g2l_m = (const int*)d_in[5];
    const int* l2l_i = (const int*)d_in[6];
    const int* g2g_i = (const int*)d_in[7];
    const int* l2g_i = (const int*)d_in[8];
    const int* g2l_i = (const int*)d_in[9];
    const float* wq_long = (const float*)d_in[10];
    const float* bq_long = (const float*)d_in[11];
    const float* wk_long = (const float*)d_in[12];
    const float* bk_long = (const float*)d_in[13];
    const float* wv_long = (const float*)d_in[14];
    const float* bv_long = (const float*)d_in[15];
    const float* wq_glob = (const float*)d_in[16];
    const float* bq_glob = (const float*)d_in[17];
    const float* wk_glob = (const float*)d_in[18];
    const float* bk_glob = (const float*)d_in[19];
    const float* wv_glob = (const float*)d_in[20];
    const float* bv_glob = (const float*)d_in[21];
    const float* rel_emb_long  = (const float*)d_in[22];
    const float* rel_bias_long = (const float*)d_in[23];
    const float* rel_emb_glob  = (const float*)d_in[24];
    const float* rel_bias_glob = (const float*)d_in[25];
    const float* wo_long = (const float*)d_in[26];
    const float* bo_long = (const float*)d_in[27];
    const float* wo_glob = (const float*)d_in[28];
    const float* bo_glob = (const float*)d_in[29];

    float *lq, *lk, *lv, *gq, *gk, *gv, *lctx, *gctx;
    cudaGetSymbolAddress((void**)&lq,   g_lq);
    cudaGetSymbolAddress((void**)&lk,   g_lk);
    cudaGetSymbolAddress((void**)&lv,   g_lv);
    cudaGetSymbolAddress((void**)&gq,   g_gq);
    cudaGetSymbolAddress((void**)&gk,   g_gk);
    cudaGetSymbolAddress((void**)&gv,   g_gv);
    cudaGetSymbolAddress((void**)&lctx, g_lctx);
    cudaGetSymbolAddress((void**)&gctx, g_gctx);

    cudaFuncSetAttribute(gemm_mma, cudaFuncAttributeMaxDynamicSharedMemorySize, GEMM_SMEM);
    cudaFuncSetAttribute(long_attn_mma, cudaFuncAttributeMaxDynamicSharedMemorySize, ATT_SMEM);
    cudaFuncSetAttribute(glob_attn_mma, cudaFuncAttributeMaxDynamicSharedMemorySize, ATT_SMEM);

    // 1) pack mask+id bytes
    {
        int nmax = Bc*Lc*Gc;
        pack_l_kernel<<<(nmax + 255)/256, 256>>>(l2l_m, l2l_i, l2g_m, l2g_i);
        int ntot = Bc*Gc*KTOTG;
        pack_g_kernel<<<(ntot + 255)/256, 256>>>(g2g_m, g2g_i, g2l_m, g2l_i);
    }

    // 2) projections
    dim3 gbig(HIDc/128, (Bc*Lc)/128);
    dim3 gsm (HIDc/64,  (Bc*Gc)/64);
    gemm_mma<<<gbig, 256, GEMM_SMEM>>>(long_input, wq_long, bq_long, lq);
    gemm_mma<<<gbig, 256, GEMM_SMEM>>>(long_input, wk_long, bk_long, lk);
    gemm_mma<<<gbig, 256, GEMM_SMEM>>>(long_input, wv_long, bv_long, lv);
    gemm_bias<64,64,8,4><<<gsm, 128>>>(global_input, wq_glob, bq_glob, gq, Bc*Gc);
    gemm_bias<64,64,8,4><<<gsm, 128>>>(global_input, wk_glob, bk_glob, gk, Bc*Gc);
    gemm_bias<64,64,8,4><<<gsm, 128>>>(global_input, wv_glob, bv_glob, gv, Bc*Gc);

    // 3) long attention
    dim3 gla(Nc, Hc, Bc);
    long_attn_mma<<<gla, 256, ATT_SMEM>>>(rel_emb_long, rel_bias_long);

    // 4) global attention + combine
    dim3 gga(2, GSPLIT, Bc*Hc);
    glob_attn_mma<<<gga, 256, ATT_SMEM>>>(rel_emb_glob, rel_bias_glob);
    glob_combine2<<<Bc*Hc*2*128, 64>>>();

    // 5) output projections
    float* out_long = (float*)d_out;
    float* out_glob = out_long + (size_t)Bc*Lc*HIDc;
    gemm_mma<<<gbig, 256, GEMM_SMEM>>>(lctx, wo_long, bo_long, out_long);
    gemm_bias<64,64,8,4><<<gsm, 128>>>(gctx, wo_glob, bo_glob, out_glob, Bc*Gc);
}